// round 4
// baseline (speedup 1.0000x reference)
#include <cuda_runtime.h>
#include <math.h>

// Problem constants
#define BB   512      // batch
#define DD   1024     // D
#define HH   4096     // H
#define TT   21       // TAU + 1
#define TAUV 20
#define KTOP 100

// ---------------------------------------------------------------------------
// Static device scratch (no allocations allowed)
// ---------------------------------------------------------------------------
__device__ float g_XpT[(size_t)TT * BB * DD];   // [t][b][d]   44 MB
__device__ float g_ZpT[(size_t)TT * BB * HH];   // [t][b][h]  176 MB
__device__ float g_Zt [(size_t)BB * HH];        // [b][h]       8 MB
// accumulators: 0=sum|Bs| 1=sum|trilM| 2=sseX 3=sseZ 4=sumAbsE 5=sum|Zt|
__device__ double g_acc[8];

// ---------------------------------------------------------------------------
__global__ void k_init() {
    if (threadIdx.x < 8) g_acc[threadIdx.x] = 0.0;
}

// Xp (B,D,T) t-fastest  ->  XpT [t][b*D+d]  (d-contiguous per t)
__global__ void k_transpose(const float* __restrict__ Xp) {
    int idx = blockIdx.x * blockDim.x + threadIdx.x;   // over B*D
    if (idx >= BB * DD) return;
    const float* s = Xp + (size_t)idx * TT;
#pragma unroll
    for (int t = 0; t < TT; t++)
        g_XpT[(size_t)t * BB * DD + idx] = s[t];
}

// ---------------------------------------------------------------------------
// GEMM 1 (NN): ZpT[t] = XpT[t] (B x D) @ F_enc (D x H)
// 64x64 tile, 256 threads, 4x4 per-thread microtile, K-tile 16.
// ---------------------------------------------------------------------------
__global__ void __launch_bounds__(256) k_zp(const float* __restrict__ Fe) {
    const int t = blockIdx.z;
    const float* A = g_XpT + (size_t)t * BB * DD;
    float*       C = g_ZpT + (size_t)t * BB * HH;

    __shared__ float Asb[16][68];   // [k][m]
    __shared__ float Bsb[16][68];   // [k][n]

    const int tid = threadIdx.x;
    const int tx = tid & 15, ty = tid >> 4;
    const int m0 = blockIdx.y * 64, n0 = blockIdx.x * 64;
    const int arow = tid >> 2, akq = tid & 3;   // A loader: 64 rows x 4 k-quads
    const int brow = tid >> 4, bq  = tid & 15;  // B loader: 16 k-rows x 16 n-quads

    float acc[4][4] = {};

    for (int k0 = 0; k0 < DD; k0 += 16) {
        float4 av = *(const float4*)(A + (size_t)(m0 + arow) * DD + k0 + akq * 4);
        Asb[akq * 4 + 0][arow] = av.x;
        Asb[akq * 4 + 1][arow] = av.y;
        Asb[akq * 4 + 2][arow] = av.z;
        Asb[akq * 4 + 3][arow] = av.w;
        float4 bv = *(const float4*)(Fe + (size_t)(k0 + brow) * HH + n0 + bq * 4);
        *(float4*)&Bsb[brow][bq * 4] = bv;
        __syncthreads();
#pragma unroll
        for (int kk = 0; kk < 16; kk++) {
            const float4 a4 = *(const float4*)&Asb[kk][ty * 4];
            const float4 b4 = *(const float4*)&Bsb[kk][tx * 4];
            const float ar[4] = {a4.x, a4.y, a4.z, a4.w};
            const float br[4] = {b4.x, b4.y, b4.z, b4.w};
#pragma unroll
            for (int i = 0; i < 4; i++)
#pragma unroll
                for (int j = 0; j < 4; j++)
                    acc[i][j] += ar[i] * br[j];
        }
        __syncthreads();
    }
#pragma unroll
    for (int i = 0; i < 4; i++) {
        float4 v = make_float4(acc[i][0], acc[i][1], acc[i][2], acc[i][3]);
        *(float4*)(C + (size_t)(m0 + ty * 4 + i) * HH + n0 + tx * 4) = v;
    }
}

// ---------------------------------------------------------------------------
// GEMM 2 (NT, fused 21 layers):
//   Zt[b,h] = sum_{l<20} sum_d Bs[l,h,d] * ZpT[19-l][b][d]
//           + sum_d tril(M,1)[h,d]      * ZpT[20][b][d]
// B operand is row-major N(h) x K(d)  -> NT GEMM. Also fuses sum|Bs| and
// sum|tril(M,1)| (accumulated only by the blockIdx.y==0 CTA column, which
// together cover every (h,d) exactly once).
// ---------------------------------------------------------------------------
__global__ void __launch_bounds__(256) k_zt(const float* __restrict__ Bsw,
                                            const float* __restrict__ Mw) {
    __shared__ float Asb[16][68];   // [k][m]
    __shared__ float Bsh[16][68];   // [k][n]
    __shared__ float red[256];

    const int tid = threadIdx.x;
    const int tx = tid & 15, ty = tid >> 4;
    const int m0 = blockIdx.y * 64, n0 = blockIdx.x * 64;
    const int arow = tid >> 2, akq = tid & 3;
    const bool doAbs = (blockIdx.y == 0);

    float acc[4][4] = {};
    float sBs = 0.f, sM = 0.f;

    for (int layer = 0; layer < TT; layer++) {
        const int tsel = (layer < TAUV) ? (TAUV - 1 - layer) : TAUV;
        const float* A  = g_ZpT + (size_t)tsel * BB * HH;
        const bool  isM = (layer == TAUV);
        const float* Bp = isM ? Mw : (Bsw + (size_t)layer * HH * HH);

        for (int k0 = 0; k0 < HH; k0 += 16) {
            float4 av = *(const float4*)(A + (size_t)(m0 + arow) * HH + k0 + akq * 4);
            Asb[akq * 4 + 0][arow] = av.x;
            Asb[akq * 4 + 1][arow] = av.y;
            Asb[akq * 4 + 2][arow] = av.z;
            Asb[akq * 4 + 3][arow] = av.w;

            float4 bv = *(const float4*)(Bp + (size_t)(n0 + arow) * HH + k0 + akq * 4);
            float bb[4] = {bv.x, bv.y, bv.z, bv.w};
            if (isM) {
                const int hg = n0 + arow;
#pragma unroll
                for (int j = 0; j < 4; j++) {
                    const int dg = k0 + akq * 4 + j;
                    if (dg > hg + 1) bb[j] = 0.f;
                }
            }
            if (doAbs) {
                const float s = fabsf(bb[0]) + fabsf(bb[1]) + fabsf(bb[2]) + fabsf(bb[3]);
                if (isM) sM += s; else sBs += s;
            }
            Bsh[akq * 4 + 0][arow] = bb[0];
            Bsh[akq * 4 + 1][arow] = bb[1];
            Bsh[akq * 4 + 2][arow] = bb[2];
            Bsh[akq * 4 + 3][arow] = bb[3];
            __syncthreads();
#pragma unroll
            for (int kk = 0; kk < 16; kk++) {
                const float4 a4 = *(const float4*)&Asb[kk][ty * 4];
                const float4 b4 = *(const float4*)&Bsh[kk][tx * 4];
                const float ar[4] = {a4.x, a4.y, a4.z, a4.w};
                const float br[4] = {b4.x, b4.y, b4.z, b4.w};
#pragma unroll
                for (int i = 0; i < 4; i++)
#pragma unroll
                    for (int j = 0; j < 4; j++)
                        acc[i][j] += ar[i] * br[j];
            }
            __syncthreads();
        }
    }
#pragma unroll
    for (int i = 0; i < 4; i++) {
        float4 v = make_float4(acc[i][0], acc[i][1], acc[i][2], acc[i][3]);
        *(float4*)(g_Zt + (size_t)(m0 + ty * 4 + i) * HH + n0 + tx * 4) = v;
    }
    if (doAbs) {
        red[tid] = sBs; __syncthreads();
        for (int s = 128; s; s >>= 1) { if (tid < s) red[tid] += red[tid + s]; __syncthreads(); }
        if (tid == 0) atomicAdd(&g_acc[0], (double)red[0]);
        __syncthreads();
        red[tid] = sM; __syncthreads();
        for (int s = 128; s; s >>= 1) { if (tid < s) red[tid] += red[tid + s]; __syncthreads(); }
        if (tid == 0) atomicAdd(&g_acc[1], (double)red[0]);
    }
}

// ---------------------------------------------------------------------------
// GEMM 3 (NN) + fused MSE: recons = Zlast (B x H) @ F_dec (H x D),
// compared directly against Xp[:,:,20]; only the sse leaves the kernel.
// ---------------------------------------------------------------------------
__global__ void __launch_bounds__(256) k_recons(const float* __restrict__ Fd,
                                                const float* __restrict__ Xp) {
    __shared__ float Asb[16][68];
    __shared__ float Bsb[16][68];
    __shared__ float red[256];

    const float* A = g_ZpT + (size_t)TAUV * BB * HH;   // Zlast, B x H
    const int tid = threadIdx.x;
    const int tx = tid & 15, ty = tid >> 4;
    const int m0 = blockIdx.y * 64, n0 = blockIdx.x * 64;
    const int arow = tid >> 2, akq = tid & 3;
    const int brow = tid >> 4, bq  = tid & 15;

    float acc[4][4] = {};

    for (int k0 = 0; k0 < HH; k0 += 16) {
        float4 av = *(const float4*)(A + (size_t)(m0 + arow) * HH + k0 + akq * 4);
        Asb[akq * 4 + 0][arow] = av.x;
        Asb[akq * 4 + 1][arow] = av.y;
        Asb[akq * 4 + 2][arow] = av.z;
        Asb[akq * 4 + 3][arow] = av.w;
        float4 bv = *(const float4*)(Fd + (size_t)(k0 + brow) * DD + n0 + bq * 4);
        *(float4*)&Bsb[brow][bq * 4] = bv;
        __syncthreads();
#pragma unroll
        for (int kk = 0; kk < 16; kk++) {
            const float4 a4 = *(const float4*)&Asb[kk][ty * 4];
            const float4 b4 = *(const float4*)&Bsb[kk][tx * 4];
            const float ar[4] = {a4.x, a4.y, a4.z, a4.w};
            const float br[4] = {b4.x, b4.y, b4.z, b4.w};
#pragma unroll
            for (int i = 0; i < 4; i++)
#pragma unroll
                for (int j = 0; j < 4; j++)
                    acc[i][j] += ar[i] * br[j];
        }
        __syncthreads();
    }
    float sse = 0.f;
#pragma unroll
    for (int i = 0; i < 4; i++)
#pragma unroll
        for (int j = 0; j < 4; j++) {
            const int b = m0 + ty * 4 + i;
            const int d = n0 + tx * 4 + j;
            const float x = Xp[((size_t)b * DD + d) * TT + TAUV];
            const float df = acc[i][j] - x;
            sse += df * df;
        }
    red[tid] = sse; __syncthreads();
    for (int s = 128; s; s >>= 1) { if (tid < s) red[tid] += red[tid + s]; __syncthreads(); }
    if (tid == 0) atomicAdd(&g_acc[2], (double)red[0]);
}

// ---------------------------------------------------------------------------
// Per-row (one block per b) exact top-100 via 8-bit radix select on |Zt| bit
// patterns, then the three masked losses.
// ---------------------------------------------------------------------------
__global__ void __launch_bounds__(256) k_topk() {
    __shared__ float    zrow[HH];          // 16 KB
    __shared__ unsigned hist[256];
    __shared__ unsigned s_prefix;
    __shared__ int      s_k;
    __shared__ float    red[256];

    const int b = blockIdx.x, tid = threadIdx.x;
    const float* zt = g_Zt + (size_t)b * HH;
    const float* zl = g_ZpT + (size_t)TAUV * BB * HH + (size_t)b * HH;

    for (int i = tid; i < HH; i += 256) zrow[i] = zt[i];
    __syncthreads();

    unsigned prefix = 0u;
    int kneed = KTOP;
    for (int shift = 24; shift >= 0; shift -= 8) {
        hist[tid] = 0u;
        __syncthreads();
        const unsigned hm = (shift == 24) ? 0u : (0xFFFFFFFFu << (shift + 8));
        for (int i = tid; i < HH; i += 256) {
            const unsigned bits = __float_as_uint(fabsf(zrow[i]));
            if ((bits & hm) == prefix) atomicAdd(&hist[(bits >> shift) & 255u], 1u);
        }
        __syncthreads();
        if (tid == 0) {
            int acc = 0;
            for (int bb = 255; bb >= 0; bb--) {
                acc += (int)hist[bb];
                if (acc >= kneed) {
                    s_prefix = prefix | ((unsigned)bb << shift);
                    s_k = kneed - (acc - (int)hist[bb]);
                    break;
                }
            }
        }
        __syncthreads();
        prefix = s_prefix;
        kneed = s_k;
        __syncthreads();
    }
    const unsigned T = prefix;     // bit pattern of the 100th largest |Zt|
    // Ties at T: keep the first `kneed` in index order (matches top_k), zero
    // the rest so the >=T test below excludes them.
    if (tid == 0) {
        int r = kneed;
        for (int i = 0; i < HH; i++) {
            if (__float_as_uint(fabsf(zrow[i])) == T) {
                if (r > 0) r--; else zrow[i] = 0.f;
            }
        }
    }
    __syncthreads();

    float sse = 0.f, sab = 0.f, saz = 0.f;
    for (int i = tid; i < HH; i += 256) {
        const float z  = zrow[i];
        const float zm = (__float_as_uint(fabsf(z)) >= T) ? z : 0.f;
        const float zv = zl[i];
        const float d  = zm - zv;
        sse += d * d;
        sab += fabsf(d);
        saz += fabsf(zm);
    }
    red[tid] = sse; __syncthreads();
    for (int s = 128; s; s >>= 1) { if (tid < s) red[tid] += red[tid + s]; __syncthreads(); }
    if (tid == 0) atomicAdd(&g_acc[3], (double)red[0]);
    __syncthreads();
    red[tid] = sab; __syncthreads();
    for (int s = 128; s; s >>= 1) { if (tid < s) red[tid] += red[tid + s]; __syncthreads(); }
    if (tid == 0) atomicAdd(&g_acc[4], (double)red[0]);
    __syncthreads();
    red[tid] = saz; __syncthreads();
    for (int s = 128; s; s >>= 1) { if (tid < s) red[tid] += red[tid + s]; __syncthreads(); }
    if (tid == 0) atomicAdd(&g_acc[5], (double)red[0]);
}

// ---------------------------------------------------------------------------
__global__ void k_final(float* __restrict__ out) {
    if (threadIdx.x == 0 && blockIdx.x == 0) {
        out[0] = (float)(g_acc[2] / ((double)BB * DD));       // loss_mse_Xt
        out[1] = (float)(g_acc[3] / ((double)BB * HH));       // loss_mse_Zt
        out[2] = (float)(g_acc[4] / ((double)BB * HH));       // loss_indep
        out[3] = (float)(g_acc[0] / ((double)HH * HH));       // loss_sparse_Bs
        out[4] = (float)(g_acc[1] / ((double)HH * HH));       // loss_sparse_M
        out[5] = (float)(g_acc[5] / ((double)BB * HH));       // loss_sparse_Zt
    }
}

// ---------------------------------------------------------------------------
extern "C" void kernel_launch(void* const* d_in, const int* in_sizes, int n_in,
                              void* d_out, int out_size) {
    (void)in_sizes; (void)n_in; (void)out_size;
    const float* Xp  = (const float*)d_in[0];
    const float* Fe  = (const float*)d_in[1];
    const float* Fd  = (const float*)d_in[2];
    const float* Bsw = (const float*)d_in[3];
    const float* Mw  = (const float*)d_in[4];
    float* out = (float*)d_out;

    k_init<<<1, 32>>>();
    k_transpose<<<(BB * DD + 255) / 256, 256>>>(Xp);

    dim3 gz(HH / 64, BB / 64, TT);
    k_zp<<<gz, 256>>>(Fe);

    dim3 gt(HH / 64, BB / 64);
    k_zt<<<gt, 256>>>(Bsw, Mw);

    dim3 gr(DD / 64, BB / 64);
    k_recons<<<gr, 256>>>(Fd, Xp);

    k_topk<<<BB, 256>>>();
    k_final<<<1, 32>>>(out);
}

// round 5
// speedup vs baseline: 1.0256x; 1.0256x over previous
#include <cuda_runtime.h>
#include <math.h>

// Problem constants
#define BB   512      // batch
#define DD   1024     // D
#define HH   4096     // H
#define TT   21       // TAU + 1
#define TAUV 20
#define KTOP 100

// ---------------------------------------------------------------------------
// Static device scratch (no allocations allowed)
// ---------------------------------------------------------------------------
__device__ float g_XpT[(size_t)TT * BB * DD];   // [t][b][d]   44 MB
__device__ float g_ZpT[(size_t)TT * BB * HH];   // [t][b][h]  176 MB
__device__ float g_Zt [(size_t)BB * HH];        // [b][h]       8 MB
// accumulators: 0=sum|Bs| 1=sum|trilM| 2=sseX 3=sseZ 4=sumAbsE 5=sum|Zt|
__device__ double g_acc[8];

// ---------------------------------------------------------------------------
__global__ void k_init() {
    if (threadIdx.x < 8) g_acc[threadIdx.x] = 0.0;
}

// Xp (B,D,T) t-fastest  ->  XpT [t][b*D+d]  (d-contiguous per t)
__global__ void k_transpose(const float* __restrict__ Xp) {
    int idx = blockIdx.x * blockDim.x + threadIdx.x;   // over B*D
    if (idx >= BB * DD) return;
    const float* s = Xp + (size_t)idx * TT;
#pragma unroll
    for (int t = 0; t < TT; t++)
        g_XpT[(size_t)t * BB * DD + idx] = s[t];
}

// ---------------------------------------------------------------------------
// GEMM 1 (NN): ZpT[t] = XpT[t] (B x D) @ F_enc (D x H)
// 128x128 tile, 256 threads, 8x8 microtile, BK=8, double-buffered smem.
// ---------------------------------------------------------------------------
__global__ void __launch_bounds__(256) k_zp(const float* __restrict__ Fe) {
    const int t = blockIdx.z;
    const float* A = g_XpT + (size_t)t * BB * DD;
    float*       C = g_ZpT + (size_t)t * BB * HH;

    __shared__ float As[2][8][132];   // [buf][k][m]
    __shared__ float Bs[2][8][132];   // [buf][k][n]

    const int tid = threadIdx.x;
    const int tx = tid & 15, ty = tid >> 4;
    const int m0 = blockIdx.y * 128, n0 = blockIdx.x * 128;
    const int lrow = tid >> 1, lq = tid & 1;     // A loader: 128 rows x 2 k-quads
    const int bkr = tid >> 5, bnq = tid & 31;    // B loader: 8 k-rows x 32 n-quads

    float acc[8][8] = {};
    const int NKT = DD / 8;

    float4 av = *(const float4*)(A + (size_t)(m0 + lrow) * DD + lq * 4);
    float4 bv = *(const float4*)(Fe + (size_t)bkr * HH + n0 + bnq * 4);

    int buf = 0;
    As[buf][lq * 4 + 0][lrow] = av.x;
    As[buf][lq * 4 + 1][lrow] = av.y;
    As[buf][lq * 4 + 2][lrow] = av.z;
    As[buf][lq * 4 + 3][lrow] = av.w;
    *(float4*)&Bs[buf][bkr][bnq * 4] = bv;
    __syncthreads();

    for (int kt = 0; kt < NKT; kt++) {
        float4 an, bn;
        if (kt + 1 < NKT) {
            const int k0 = (kt + 1) * 8;
            an = *(const float4*)(A + (size_t)(m0 + lrow) * DD + k0 + lq * 4);
            bn = *(const float4*)(Fe + (size_t)(k0 + bkr) * HH + n0 + bnq * 4);
        }
#pragma unroll
        for (int kk = 0; kk < 8; kk++) {
            float ar[8], br[8];
            *(float4*)(ar)     = *(const float4*)&As[buf][kk][ty * 4];
            *(float4*)(ar + 4) = *(const float4*)&As[buf][kk][64 + ty * 4];
            *(float4*)(br)     = *(const float4*)&Bs[buf][kk][tx * 4];
            *(float4*)(br + 4) = *(const float4*)&Bs[buf][kk][64 + tx * 4];
#pragma unroll
            for (int i = 0; i < 8; i++)
#pragma unroll
                for (int j = 0; j < 8; j++)
                    acc[i][j] += ar[i] * br[j];
        }
        if (kt + 1 < NKT) {
            buf ^= 1;
            As[buf][lq * 4 + 0][lrow] = an.x;
            As[buf][lq * 4 + 1][lrow] = an.y;
            As[buf][lq * 4 + 2][lrow] = an.z;
            As[buf][lq * 4 + 3][lrow] = an.w;
            *(float4*)&Bs[buf][bkr][bnq * 4] = bn;
        }
        __syncthreads();
    }
#pragma unroll
    for (int i = 0; i < 8; i++) {
        const int gm = m0 + ((i < 4) ? (ty * 4 + i) : (64 + ty * 4 + i - 4));
        *(float4*)(C + (size_t)gm * HH + n0 + tx * 4) =
            make_float4(acc[i][0], acc[i][1], acc[i][2], acc[i][3]);
        *(float4*)(C + (size_t)gm * HH + n0 + 64 + tx * 4) =
            make_float4(acc[i][4], acc[i][5], acc[i][6], acc[i][7]);
    }
}

// ---------------------------------------------------------------------------
// GEMM 2 (NT, fused 21 layers):
//   Zt[b,h] = sum_{l<20} sum_d Bs[l,h,d] * ZpT[19-l][b][d]
//           + sum_d tril(M,1)[h,d]      * ZpT[20][b][d]
// 128x128 tile, 8x8 microtile, BK=8, double-buffered. Fuses sum|Bs| and
// sum|tril(M,1)| at global-load time (blockIdx.y==0 CTA column covers every
// (h,d) exactly once; double buffering fetches each element exactly once).
// ---------------------------------------------------------------------------
__global__ void __launch_bounds__(256) k_zt(const float* __restrict__ Bsw,
                                            const float* __restrict__ Mw) {
    __shared__ float As[2][8][132];   // [buf][k][m]  (m = batch)
    __shared__ float Bsh[2][8][132];  // [buf][k][n]  (n = h)
    __shared__ float red[256];

    const int tid = threadIdx.x;
    const int tx = tid & 15, ty = tid >> 4;
    const int m0 = blockIdx.y * 128, n0 = blockIdx.x * 128;
    const int lrow = tid >> 1, lq = tid & 1;
    const bool doAbs = (blockIdx.y == 0);

    float acc[8][8] = {};
    float sBs = 0.f, sM = 0.f;
    const int NKT = TT * (HH / 8);   // 10752

    auto fetch = [&](int kt, float4& av, float4& bv) {
        const int layer = kt >> 9;            // HH/8 = 512
        const int k0 = (kt & 511) << 3;
        const int tsel = (layer < TAUV) ? (TAUV - 1 - layer) : TAUV;
        const float* A = g_ZpT + (size_t)tsel * BB * HH;
        av = *(const float4*)(A + (size_t)(m0 + lrow) * HH + k0 + lq * 4);
        const float* Bp = (layer == TAUV) ? Mw : (Bsw + (size_t)layer * HH * HH);
        bv = *(const float4*)(Bp + (size_t)(n0 + lrow) * HH + k0 + lq * 4);
        if (layer == TAUV) {
            const int hg = n0 + lrow;
            float* bb = (float*)&bv;
#pragma unroll
            for (int j = 0; j < 4; j++)
                if (k0 + lq * 4 + j > hg + 1) bb[j] = 0.f;
            if (doAbs) sM += fabsf(bv.x) + fabsf(bv.y) + fabsf(bv.z) + fabsf(bv.w);
        } else if (doAbs) {
            sBs += fabsf(bv.x) + fabsf(bv.y) + fabsf(bv.z) + fabsf(bv.w);
        }
    };

    float4 av, bv;
    fetch(0, av, bv);
    int buf = 0;
    As[buf][lq * 4 + 0][lrow] = av.x;
    As[buf][lq * 4 + 1][lrow] = av.y;
    As[buf][lq * 4 + 2][lrow] = av.z;
    As[buf][lq * 4 + 3][lrow] = av.w;
    Bsh[buf][lq * 4 + 0][lrow] = bv.x;
    Bsh[buf][lq * 4 + 1][lrow] = bv.y;
    Bsh[buf][lq * 4 + 2][lrow] = bv.z;
    Bsh[buf][lq * 4 + 3][lrow] = bv.w;
    __syncthreads();

    for (int kt = 0; kt < NKT; kt++) {
        float4 an, bn;
        if (kt + 1 < NKT) fetch(kt + 1, an, bn);
#pragma unroll
        for (int kk = 0; kk < 8; kk++) {
            float ar[8], br[8];
            *(float4*)(ar)     = *(const float4*)&As[buf][kk][ty * 4];
            *(float4*)(ar + 4) = *(const float4*)&As[buf][kk][64 + ty * 4];
            *(float4*)(br)     = *(const float4*)&Bsh[buf][kk][tx * 4];
            *(float4*)(br + 4) = *(const float4*)&Bsh[buf][kk][64 + tx * 4];
#pragma unroll
            for (int i = 0; i < 8; i++)
#pragma unroll
                for (int j = 0; j < 8; j++)
                    acc[i][j] += ar[i] * br[j];
        }
        if (kt + 1 < NKT) {
            buf ^= 1;
            As[buf][lq * 4 + 0][lrow] = an.x;
            As[buf][lq * 4 + 1][lrow] = an.y;
            As[buf][lq * 4 + 2][lrow] = an.z;
            As[buf][lq * 4 + 3][lrow] = an.w;
            Bsh[buf][lq * 4 + 0][lrow] = bn.x;
            Bsh[buf][lq * 4 + 1][lrow] = bn.y;
            Bsh[buf][lq * 4 + 2][lrow] = bn.z;
            Bsh[buf][lq * 4 + 3][lrow] = bn.w;
        }
        __syncthreads();
    }

#pragma unroll
    for (int i = 0; i < 8; i++) {
        const int gm = m0 + ((i < 4) ? (ty * 4 + i) : (64 + ty * 4 + i - 4));
        *(float4*)(g_Zt + (size_t)gm * HH + n0 + tx * 4) =
            make_float4(acc[i][0], acc[i][1], acc[i][2], acc[i][3]);
        *(float4*)(g_Zt + (size_t)gm * HH + n0 + 64 + tx * 4) =
            make_float4(acc[i][4], acc[i][5], acc[i][6], acc[i][7]);
    }

    if (doAbs) {
        red[tid] = sBs; __syncthreads();
        for (int s = 128; s; s >>= 1) { if (tid < s) red[tid] += red[tid + s]; __syncthreads(); }
        if (tid == 0) atomicAdd(&g_acc[0], (double)red[0]);
        __syncthreads();
        red[tid] = sM; __syncthreads();
        for (int s = 128; s; s >>= 1) { if (tid < s) red[tid] += red[tid + s]; __syncthreads(); }
        if (tid == 0) atomicAdd(&g_acc[1], (double)red[0]);
    }
}

// ---------------------------------------------------------------------------
// GEMM 3 (NN) + fused MSE: recons = Zlast (B x H) @ F_dec (H x D),
// compared directly against Xp[:,:,20]; only the sse leaves the kernel.
// (64x64 tile — this GEMM is only ~1% of total FLOPs.)
// ---------------------------------------------------------------------------
__global__ void __launch_bounds__(256) k_recons(const float* __restrict__ Fd,
                                                const float* __restrict__ Xp) {
    __shared__ float Asb[16][68];
    __shared__ float Bsb[16][68];
    __shared__ float red[256];

    const float* A = g_ZpT + (size_t)TAUV * BB * HH;   // Zlast, B x H
    const int tid = threadIdx.x;
    const int tx = tid & 15, ty = tid >> 4;
    const int m0 = blockIdx.y * 64, n0 = blockIdx.x * 64;
    const int arow = tid >> 2, akq = tid & 3;
    const int brow = tid >> 4, bq  = tid & 15;

    float acc[4][4] = {};

    for (int k0 = 0; k0 < HH; k0 += 16) {
        float4 av = *(const float4*)(A + (size_t)(m0 + arow) * HH + k0 + akq * 4);
        Asb[akq * 4 + 0][arow] = av.x;
        Asb[akq * 4 + 1][arow] = av.y;
        Asb[akq * 4 + 2][arow] = av.z;
        Asb[akq * 4 + 3][arow] = av.w;
        float4 bv = *(const float4*)(Fd + (size_t)(k0 + brow) * DD + n0 + bq * 4);
        *(float4*)&Bsb[brow][bq * 4] = bv;
        __syncthreads();
#pragma unroll
        for (int kk = 0; kk < 16; kk++) {
            const float4 a4 = *(const float4*)&Asb[kk][ty * 4];
            const float4 b4 = *(const float4*)&Bsb[kk][tx * 4];
            const float ar[4] = {a4.x, a4.y, a4.z, a4.w};
            const float br[4] = {b4.x, b4.y, b4.z, b4.w};
#pragma unroll
            for (int i = 0; i < 4; i++)
#pragma unroll
                for (int j = 0; j < 4; j++)
                    acc[i][j] += ar[i] * br[j];
        }
        __syncthreads();
    }
    float sse = 0.f;
#pragma unroll
    for (int i = 0; i < 4; i++)
#pragma unroll
        for (int j = 0; j < 4; j++) {
            const int b = m0 + ty * 4 + i;
            const int d = n0 + tx * 4 + j;
            const float x = Xp[((size_t)b * DD + d) * TT + TAUV];
            const float df = acc[i][j] - x;
            sse += df * df;
        }
    red[tid] = sse; __syncthreads();
    for (int s = 128; s; s >>= 1) { if (tid < s) red[tid] += red[tid + s]; __syncthreads(); }
    if (tid == 0) atomicAdd(&g_acc[2], (double)red[0]);
}

// ---------------------------------------------------------------------------
// Per-row (one block per b) exact top-100 via 8-bit radix select on |Zt| bit
// patterns, then the three masked losses.
// ---------------------------------------------------------------------------
__global__ void __launch_bounds__(256) k_topk() {
    __shared__ float    zrow[HH];          // 16 KB
    __shared__ unsigned hist[256];
    __shared__ unsigned s_prefix;
    __shared__ int      s_k;
    __shared__ float    red[256];

    const int b = blockIdx.x, tid = threadIdx.x;
    const float* zt = g_Zt + (size_t)b * HH;
    const float* zl = g_ZpT + (size_t)TAUV * BB * HH + (size_t)b * HH;

    for (int i = tid; i < HH; i += 256) zrow[i] = zt[i];
    __syncthreads();

    unsigned prefix = 0u;
    int kneed = KTOP;
    for (int shift = 24; shift >= 0; shift -= 8) {
        hist[tid] = 0u;
        __syncthreads();
        const unsigned hm = (shift == 24) ? 0u : (0xFFFFFFFFu << (shift + 8));
        for (int i = tid; i < HH; i += 256) {
            const unsigned bits = __float_as_uint(fabsf(zrow[i]));
            if ((bits & hm) == prefix) atomicAdd(&hist[(bits >> shift) & 255u], 1u);
        }
        __syncthreads();
        if (tid == 0) {
            int acc = 0;
            for (int bb = 255; bb >= 0; bb--) {
                acc += (int)hist[bb];
                if (acc >= kneed) {
                    s_prefix = prefix | ((unsigned)bb << shift);
                    s_k = kneed - (acc - (int)hist[bb]);
                    break;
                }
            }
        }
        __syncthreads();
        prefix = s_prefix;
        kneed = s_k;
        __syncthreads();
    }
    const unsigned T = prefix;     // bit pattern of the 100th largest |Zt|
    // Ties at T: keep the first `kneed` in index order (matches top_k), zero
    // the rest so the >=T test below excludes them.
    if (tid == 0) {
        int r = kneed;
        for (int i = 0; i < HH; i++) {
            if (__float_as_uint(fabsf(zrow[i])) == T) {
                if (r > 0) r--; else zrow[i] = 0.f;
            }
        }
    }
    __syncthreads();

    float sse = 0.f, sab = 0.f, saz = 0.f;
    for (int i = tid; i < HH; i += 256) {
        const float z  = zrow[i];
        const float zm = (__float_as_uint(fabsf(z)) >= T) ? z : 0.f;
        const float zv = zl[i];
        const float d  = zm - zv;
        sse += d * d;
        sab += fabsf(d);
        saz += fabsf(zm);
    }
    red[tid] = sse; __syncthreads();
    for (int s = 128; s; s >>= 1) { if (tid < s) red[tid] += red[tid + s]; __syncthreads(); }
    if (tid == 0) atomicAdd(&g_acc[3], (double)red[0]);
    __syncthreads();
    red[tid] = sab; __syncthreads();
    for (int s = 128; s; s >>= 1) { if (tid < s) red[tid] += red[tid + s]; __syncthreads(); }
    if (tid == 0) atomicAdd(&g_acc[4], (double)red[0]);
    __syncthreads();
    red[tid] = saz; __syncthreads();
    for (int s = 128; s; s >>= 1) { if (tid < s) red[tid] += red[tid + s]; __syncthreads(); }
    if (tid == 0) atomicAdd(&g_acc[5], (double)red[0]);
}

// ---------------------------------------------------------------------------
__global__ void k_final(float* __restrict__ out) {
    if (threadIdx.x == 0 && blockIdx.x == 0) {
        out[0] = (float)(g_acc[2] / ((double)BB * DD));       // loss_mse_Xt
        out[1] = (float)(g_acc[3] / ((double)BB * HH));       // loss_mse_Zt
        out[2] = (float)(g_acc[4] / ((double)BB * HH));       // loss_indep
        out[3] = (float)(g_acc[0] / ((double)HH * HH));       // loss_sparse_Bs
        out[4] = (float)(g_acc[1] / ((double)HH * HH));       // loss_sparse_M
        out[5] = (float)(g_acc[5] / ((double)BB * HH));       // loss_sparse_Zt
    }
}

// ---------------------------------------------------------------------------
extern "C" void kernel_launch(void* const* d_in, const int* in_sizes, int n_in,
                              void* d_out, int out_size) {
    (void)in_sizes; (void)n_in; (void)out_size;
    const float* Xp  = (const float*)d_in[0];
    const float* Fe  = (const float*)d_in[1];
    const float* Fd  = (const float*)d_in[2];
    const float* Bsw = (const float*)d_in[3];
    const float* Mw  = (const float*)d_in[4];
    float* out = (float*)d_out;

    k_init<<<1, 32>>>();
    k_transpose<<<(BB * DD + 255) / 256, 256>>>(Xp);

    dim3 gz(HH / 128, BB / 128, TT);
    k_zp<<<gz, 256>>>(Fe);

    dim3 gt(HH / 128, BB / 128);
    k_zt<<<gt, 256>>>(Bsw, Mw);

    dim3 gr(DD / 64, BB / 64);
    k_recons<<<gr, 256>>>(Fd, Xp);

    k_topk<<<BB, 256>>>();
    k_final<<<1, 32>>>(out);
}

// round 7
// speedup vs baseline: 2.5431x; 2.4797x over previous
#include <cuda_runtime.h>
#include <cuda_bf16.h>
#include <cstdint>
#include <math.h>

// Problem constants
#define BB   512
#define DD   1024
#define HH   4096
#define TT   21
#define TAUV 20
#define KTOP 100
#define KTOT (TT * HH)        // 86016 = fused contraction length for k_zt
#define BK   32
#define SST  40               // smem k-stride in bf16 (80 B = 5*16B, ldmatrix-friendly)
#define TEN_BYTES (128 * SST * 2)     // 10240 B per tensor per stage
#define STAGE_BYTES (4 * TEN_BYTES)   // Ah|Al|Bh|Bl
#define SMEM_DYN (2 * STAGE_BYTES)    // 81920

// ---------------------------------------------------------------------------
// Static device scratch (no allocations allowed)
// ---------------------------------------------------------------------------
__device__ __nv_bfloat16 g_Xh[(size_t)TT * BB * DD];   // X hi  [t][b][d]
__device__ __nv_bfloat16 g_Xl[(size_t)TT * BB * DD];   // X lo
__device__ __nv_bfloat16 g_Feh[(size_t)HH * DD];       // F_enc^T hi [h][d]
__device__ __nv_bfloat16 g_Fel[(size_t)HH * DD];       // F_enc^T lo
__device__ __nv_bfloat16 g_Ah[(size_t)BB * KTOT];      // Zp hi  [b][layer*H+h']
__device__ __nv_bfloat16 g_Al[(size_t)BB * KTOT];      // Zp lo
__device__ __nv_bfloat16 g_Bh[(size_t)HH * KTOT];      // Bs/trilM hi [h][layer*H+d]
__device__ __nv_bfloat16 g_Bl[(size_t)HH * KTOT];      // Bs/trilM lo
__device__ float g_Zlast[(size_t)BB * HH];
__device__ float g_Zt   [(size_t)BB * HH];
// 0=sum|Bs| 1=sum|trilM| 2=sseX 3=sseZ 4=sumAbsE 5=sum|Zt|
__device__ double g_acc[8];

// ---------------------------------------------------------------------------
// PTX helpers (base-target only: cp.async / ldmatrix / mma.sync)
// ---------------------------------------------------------------------------
__device__ __forceinline__ uint32_t smem_u32(const void* p) {
    uint32_t a;
    asm("{ .reg .u64 t; cvta.to.shared.u64 t, %1; cvt.u32.u64 %0, t; }"
        : "=r"(a) : "l"(p));
    return a;
}
__device__ __forceinline__ void cp_async16(uint32_t saddr, const void* gaddr) {
    asm volatile("cp.async.cg.shared.global [%0], [%1], 16;"
                 :: "r"(saddr), "l"(gaddr) : "memory");
}
__device__ __forceinline__ void cp_commit() {
    asm volatile("cp.async.commit_group;" ::: "memory");
}
__device__ __forceinline__ void cp_wait1() {
    asm volatile("cp.async.wait_group 1;" ::: "memory");
}
__device__ __forceinline__ void cp_wait0() {
    asm volatile("cp.async.wait_group 0;" ::: "memory");
}
__device__ __forceinline__ void ldsm_x4(uint32_t* r, uint32_t addr) {
    asm volatile("ldmatrix.sync.aligned.m8n8.x4.shared.b16 {%0,%1,%2,%3}, [%4];"
                 : "=r"(r[0]), "=r"(r[1]), "=r"(r[2]), "=r"(r[3]) : "r"(addr));
}
__device__ __forceinline__ void ldsm_x2(uint32_t* r, uint32_t addr) {
    asm volatile("ldmatrix.sync.aligned.m8n8.x2.shared.b16 {%0,%1}, [%2];"
                 : "=r"(r[0]), "=r"(r[1]) : "r"(addr));
}
__device__ __forceinline__ void mma_16816(float* c, const uint32_t* a, const uint32_t* b) {
    asm volatile(
        "mma.sync.aligned.m16n8k16.row.col.f32.bf16.bf16.f32 "
        "{%0,%1,%2,%3}, {%4,%5,%6,%7}, {%8,%9}, {%0,%1,%2,%3};"
        : "+f"(c[0]), "+f"(c[1]), "+f"(c[2]), "+f"(c[3])
        : "r"(a[0]), "r"(a[1]), "r"(a[2]), "r"(a[3]), "r"(b[0]), "r"(b[1]));
}

// ---------------------------------------------------------------------------
// Shared mma.sync mainloop: acc[4][4][4] (per-thread) accumulates
//   Ah*Bh + Ah*Bl + Al*Bh  over K = KT.  CTA 128x128, 8 warps (2m x 4n),
//   warp tile 64x32, BK=32, cp.async double-buffered smem.
// A_* : [128 m-rows][KT] k-contig.  B_* : [128 n-rows][KT] k-contig.
// ---------------------------------------------------------------------------
template <int KT>
__device__ __forceinline__ void mma_mainloop(
    const __nv_bfloat16* __restrict__ A_h, const __nv_bfloat16* __restrict__ A_l,
    const __nv_bfloat16* __restrict__ B_h, const __nv_bfloat16* __restrict__ B_l,
    char* smem, float acc[4][4][4])
{
    const int tid  = threadIdx.x;
    const int lane = tid & 31, warp = tid >> 5;
    const int wm = warp & 1, wn = warp >> 1;
    const uint32_t sbase = smem_u32(smem);

    // Loader: each thread covers one row (tid>>1) and a 16-wide k half.
    const int lrow = tid >> 1;
    const int lk   = (tid & 1) * 16;
    const size_t grow = (size_t)lrow * KT + lk;

    constexpr int NKT = KT / BK;

    auto issue_stage = [&](int kt, int s) {
        const size_t kb = grow + (size_t)kt * BK;
        const uint32_t so = sbase + s * STAGE_BYTES + (lrow * SST + lk) * 2;
        cp_async16(so + 0 * TEN_BYTES,      A_h + kb);
        cp_async16(so + 0 * TEN_BYTES + 16, A_h + kb + 8);
        cp_async16(so + 1 * TEN_BYTES,      A_l + kb);
        cp_async16(so + 1 * TEN_BYTES + 16, A_l + kb + 8);
        cp_async16(so + 2 * TEN_BYTES,      B_h + kb);
        cp_async16(so + 2 * TEN_BYTES + 16, B_h + kb + 8);
        cp_async16(so + 3 * TEN_BYTES,      B_l + kb);
        cp_async16(so + 3 * TEN_BYTES + 16, B_l + kb + 8);
    };

    // ldmatrix per-lane offsets
    const int arow = lane & 15;            // A: m within 16
    const int akc  = (lane >> 4) * 8;      // A: k sub-column
    const int brow = lane & 7;             // B: n within 8
    const int bkc  = ((lane >> 3) & 1) * 8;

    issue_stage(0, 0);
    cp_commit();

    for (int kt = 0; kt < NKT; kt++) {
        const int s = kt & 1;
        if (kt + 1 < NKT) { issue_stage(kt + 1, s ^ 1); cp_commit(); cp_wait1(); }
        else              { cp_wait0(); }
        __syncthreads();

        const uint32_t tb = sbase + s * STAGE_BYTES;
#pragma unroll
        for (int kk = 0; kk < 2; kk++) {
            uint32_t ah[4][4], al[4][4], bh[4][2], bl[4][2];
#pragma unroll
            for (int mi = 0; mi < 4; mi++) {
                const uint32_t ad = tb +
                    ((wm * 64 + mi * 16 + arow) * SST + kk * 16 + akc) * 2;
                ldsm_x4(ah[mi], ad);
                ldsm_x4(al[mi], ad + TEN_BYTES);
            }
#pragma unroll
            for (int ni = 0; ni < 4; ni++) {
                const uint32_t bd = tb + 2 * TEN_BYTES +
                    ((wn * 32 + ni * 8 + brow) * SST + kk * 16 + bkc) * 2;
                ldsm_x2(bh[ni], bd);
                ldsm_x2(bl[ni], bd + TEN_BYTES);
            }
#pragma unroll
            for (int mi = 0; mi < 4; mi++)
#pragma unroll
                for (int ni = 0; ni < 4; ni++) {
                    mma_16816(acc[mi][ni], ah[mi], bh[ni]);
                    mma_16816(acc[mi][ni], ah[mi], bl[ni]);
                    mma_16816(acc[mi][ni], al[mi], bh[ni]);
                }
        }
        __syncthreads();
    }
}

// ---------------------------------------------------------------------------
__global__ void k_init() {
    if (threadIdx.x < 8) g_acc[threadIdx.x] = 0.0;
}

// Xp (B,D,T) t-fastest  ->  bf16 hi/lo [t][b][d]
__global__ void k_conv_x(const float* __restrict__ Xp) {
    int idx = blockIdx.x * blockDim.x + threadIdx.x;
    if (idx >= BB * DD) return;
    const float* s = Xp + (size_t)idx * TT;
#pragma unroll
    for (int t = 0; t < TT; t++) {
        const float v = s[t];
        const __nv_bfloat16 h = __float2bfloat16_rn(v);
        const __nv_bfloat16 l = __float2bfloat16_rn(v - __bfloat162float(h));
        g_Xh[(size_t)t * BB * DD + idx] = h;
        g_Xl[(size_t)t * BB * DD + idx] = l;
    }
}

// F_enc (D,H) -> transposed bf16 hi/lo [h][d]
__global__ void k_conv_fe(const float* __restrict__ Fe) {
    __shared__ float tile[32][33];
    const int d0 = blockIdx.x * 32, h0 = blockIdx.y * 32;
    for (int r = threadIdx.y; r < 32; r += 8)
        tile[r][threadIdx.x] = Fe[(size_t)(d0 + r) * HH + h0 + threadIdx.x];
    __syncthreads();
    for (int r = threadIdx.y; r < 32; r += 8) {
        const float v = tile[threadIdx.x][r];
        const __nv_bfloat16 h = __float2bfloat16_rn(v);
        const __nv_bfloat16 l = __float2bfloat16_rn(v - __bfloat162float(h));
        const size_t o = (size_t)(h0 + r) * DD + d0 + threadIdx.x;
        g_Feh[o] = h;
        g_Fel[o] = l;
    }
}

// Bs (20,H,H) + tril(M,1) -> bf16 hi/lo [h][layer*H+d], fused |Bs| / |M| sums
__global__ void __launch_bounds__(256) k_convB(const float* __restrict__ Bsw,
                                               const float* __restrict__ Mw) {
    __shared__ float red[256];
    const size_t total = (size_t)TT * HH * (HH / 4);   // float4 units
    float sBs = 0.f, sM = 0.f;
    for (size_t u = blockIdx.x * 256 + threadIdx.x; u < total;
         u += (size_t)gridDim.x * 256) {
        const int d4 = (int)(u & 1023);
        const int h  = (int)((u >> 10) & 4095);
        const int l  = (int)(u >> 22);
        float4 v;
        if (l < TAUV) {
            v = *(const float4*)(Bsw + (((size_t)l * HH + h) * HH + d4 * 4));
            sBs += fabsf(v.x) + fabsf(v.y) + fabsf(v.z) + fabsf(v.w);
        } else {
            v = *(const float4*)(Mw + ((size_t)h * HH + d4 * 4));
            float* e = (float*)&v;
#pragma unroll
            for (int j = 0; j < 4; j++)
                if (d4 * 4 + j > h + 1) e[j] = 0.f;
            sM += fabsf(v.x) + fabsf(v.y) + fabsf(v.z) + fabsf(v.w);
        }
        __nv_bfloat16 h0 = __float2bfloat16_rn(v.x), h1 = __float2bfloat16_rn(v.y);
        __nv_bfloat16 h2 = __float2bfloat16_rn(v.z), h3 = __float2bfloat16_rn(v.w);
        __nv_bfloat16 l0 = __float2bfloat16_rn(v.x - __bfloat162float(h0));
        __nv_bfloat16 l1 = __float2bfloat16_rn(v.y - __bfloat162float(h1));
        __nv_bfloat16 l2 = __float2bfloat16_rn(v.z - __bfloat162float(h2));
        __nv_bfloat16 l3 = __float2bfloat16_rn(v.w - __bfloat162float(h3));
        const size_t o = (size_t)h * KTOT + (size_t)l * HH + d4 * 4;
        union { __nv_bfloat162 b; uint32_t u; } p0, p1, q0, q1;
        p0.b = __halves2bfloat162(h0, h1); p1.b = __halves2bfloat162(h2, h3);
        q0.b = __halves2bfloat162(l0, l1); q1.b = __halves2bfloat162(l2, l3);
        *(uint2*)(g_Bh + o) = make_uint2(p0.u, p1.u);
        *(uint2*)(g_Bl + o) = make_uint2(q0.u, q1.u);
    }
    const int tid = threadIdx.x;
    red[tid] = sBs; __syncthreads();
    for (int s = 128; s; s >>= 1) { if (tid < s) red[tid] += red[tid + s]; __syncthreads(); }
    if (tid == 0) atomicAdd(&g_acc[0], (double)red[0]);
    __syncthreads();
    red[tid] = sM; __syncthreads();
    for (int s = 128; s; s >>= 1) { if (tid < s) red[tid] += red[tid + s]; __syncthreads(); }
    if (tid == 0) atomicAdd(&g_acc[1], (double)red[0]);
}

// ---------------------------------------------------------------------------
// GEMM 1 (mma.sync): Zp[t] = X[t] (B x D) @ F_enc^T (H x D)^T per 128x128 tile.
// Epilogue emits Zp as bf16 hi/lo into the k_zt A layout (flip baked in) and
// fp32 Z_last for t = TAU.
// ---------------------------------------------------------------------------
__global__ void __launch_bounds__(256, 1) k_zp_mma() {
    extern __shared__ char smem[];
    const int tid = threadIdx.x;
    const int lane = tid & 31, warp = tid >> 5;
    const int wm = warp & 1, wn = warp >> 1;
    const int t = blockIdx.z;
    const int m0 = blockIdx.y * 128, n0 = blockIdx.x * 128;

    float acc[4][4][4] = {};
    mma_mainloop<DD>(g_Xh + ((size_t)t * BB + m0) * DD,
                     g_Xl + ((size_t)t * BB + m0) * DD,
                     g_Feh + (size_t)n0 * DD,
                     g_Fel + (size_t)n0 * DD,
                     smem, acc);

    const int layer = (t < TAUV) ? (TAUV - 1 - t) : TAUV;
    const int mb = m0 + wm * 64 + (lane >> 2);
    const int nb = n0 + wn * 32 + (lane & 3) * 2;
#pragma unroll
    for (int mi = 0; mi < 4; mi++)
#pragma unroll
        for (int ni = 0; ni < 4; ni++)
#pragma unroll
            for (int half = 0; half < 2; half++) {
                const int m = mb + mi * 16 + half * 8;
                const int n = nb + ni * 8;
                const float f0 = acc[mi][ni][half * 2];
                const float f1 = acc[mi][ni][half * 2 + 1];
                const __nv_bfloat16 h0 = __float2bfloat16_rn(f0);
                const __nv_bfloat16 h1 = __float2bfloat16_rn(f1);
                const __nv_bfloat16 l0 = __float2bfloat16_rn(f0 - __bfloat162float(h0));
                const __nv_bfloat16 l1 = __float2bfloat16_rn(f1 - __bfloat162float(h1));
                union { __nv_bfloat162 b; uint32_t u; } ph, pl;
                ph.b = __halves2bfloat162(h0, h1);
                pl.b = __halves2bfloat162(l0, l1);
                const size_t o = (size_t)m * KTOT + (size_t)layer * HH + n;
                *(uint32_t*)(g_Ah + o) = ph.u;
                *(uint32_t*)(g_Al + o) = pl.u;
                if (t == TAUV)
                    *(float2*)(g_Zlast + (size_t)m * HH + n) = make_float2(f0, f1);
            }
}

// ---------------------------------------------------------------------------
// GEMM 2 (mma.sync, fused): Zt (B x H) over K = 21 * 4096 (all layers + M).
// ---------------------------------------------------------------------------
__global__ void __launch_bounds__(256, 1) k_zt_mma() {
    extern __shared__ char smem[];
    const int tid = threadIdx.x;
    const int lane = tid & 31, warp = tid >> 5;
    const int wm = warp & 1, wn = warp >> 1;
    const int m0 = blockIdx.y * 128, n0 = blockIdx.x * 128;

    float acc[4][4][4] = {};
    mma_mainloop<KTOT>(g_Ah + (size_t)m0 * KTOT,
                       g_Al + (size_t)m0 * KTOT,
                       g_Bh + (size_t)n0 * KTOT,
                       g_Bl + (size_t)n0 * KTOT,
                       smem, acc);

    const int mb = m0 + wm * 64 + (lane >> 2);
    const int nb = n0 + wn * 32 + (lane & 3) * 2;
#pragma unroll
    for (int mi = 0; mi < 4; mi++)
#pragma unroll
        for (int ni = 0; ni < 4; ni++)
#pragma unroll
            for (int half = 0; half < 2; half++) {
                const int m = mb + mi * 16 + half * 8;
                const int n = nb + ni * 8;
                *(float2*)(g_Zt + (size_t)m * HH + n) =
                    make_float2(acc[mi][ni][half * 2], acc[mi][ni][half * 2 + 1]);
            }
}

// ---------------------------------------------------------------------------
// GEMM 3 (SIMT fp32) + fused MSE: recons = Z_last (B x H) @ F_dec (H x D)
// ---------------------------------------------------------------------------
__global__ void __launch_bounds__(256) k_recons(const float* __restrict__ Fd,
                                                const float* __restrict__ Xp) {
    __shared__ float Asb[16][68];
    __shared__ float Bsb[16][68];
    __shared__ float red[256];

    const float* A = g_Zlast;
    const int tid = threadIdx.x;
    const int tx = tid & 15, ty = tid >> 4;
    const int m0 = blockIdx.y * 64, n0 = blockIdx.x * 64;
    const int arow = tid >> 2, akq = tid & 3;
    const int brow = tid >> 4, bq  = tid & 15;

    float acc[4][4] = {};

    for (int k0 = 0; k0 < HH; k0 += 16) {
        float4 av = *(const float4*)(A + (size_t)(m0 + arow) * HH + k0 + akq * 4);
        Asb[akq * 4 + 0][arow] = av.x;
        Asb[akq * 4 + 1][arow] = av.y;
        Asb[akq * 4 + 2][arow] = av.z;
        Asb[akq * 4 + 3][arow] = av.w;
        float4 bv = *(const float4*)(Fd + (size_t)(k0 + brow) * DD + n0 + bq * 4);
        *(float4*)&Bsb[brow][bq * 4] = bv;
        __syncthreads();
#pragma unroll
        for (int kk = 0; kk < 16; kk++) {
            const float4 a4 = *(const float4*)&Asb[kk][ty * 4];
            const float4 b4 = *(const float4*)&Bsb[kk][tx * 4];
            const float ar[4] = {a4.x, a4.y, a4.z, a4.w};
            const float br[4] = {b4.x, b4.y, b4.z, b4.w};
#pragma unroll
            for (int i = 0; i < 4; i++)
#pragma unroll
                for (int j = 0; j < 4; j++)
                    acc[i][j] += ar[i] * br[j];
        }
        __syncthreads();
    }
    float sse = 0.f;
#pragma unroll
    for (int i = 0; i < 4; i++)
#pragma unroll
        for (int j = 0; j < 4; j++) {
            const int b = m0 + ty * 4 + i;
            const int d = n0 + tx * 4 + j;
            const float x = Xp[((size_t)b * DD + d) * TT + TAUV];
            const float df = acc[i][j] - x;
            sse += df * df;
        }
    red[tid] = sse; __syncthreads();
    for (int s = 128; s; s >>= 1) { if (tid < s) red[tid] += red[tid + s]; __syncthreads(); }
    if (tid == 0) atomicAdd(&g_acc[2], (double)red[0]);
}

// ---------------------------------------------------------------------------
// Per-row exact top-100 via 8-bit radix select on |Zt|, then masked losses.
// ---------------------------------------------------------------------------
__global__ void __launch_bounds__(256) k_topk() {
    __shared__ float    zrow[HH];
    __shared__ unsigned hist[256];
    __shared__ unsigned s_prefix;
    __shared__ int      s_k;
    __shared__ float    red[256];

    const int b = blockIdx.x, tid = threadIdx.x;
    const float* zt = g_Zt + (size_t)b * HH;
    const float* zl = g_Zlast + (size_t)b * HH;

    for (int i = tid; i < HH; i += 256) zrow[i] = zt[i];
    __syncthreads();

    unsigned prefix = 0u;
    int kneed = KTOP;
    for (int shift = 24; shift >= 0; shift -= 8) {
        hist[tid] = 0u;
        __syncthreads();
        const unsigned hm = (shift == 24) ? 0u : (0xFFFFFFFFu << (shift + 8));
        for (int i = tid; i < HH; i += 256) {
            const unsigned bits = __float_as_uint(fabsf(zrow[i]));
            if ((bits & hm) == prefix) atomicAdd(&hist[(bits >> shift) & 255u], 1u);
        }
        __syncthreads();
        if (tid == 0) {
            int acc = 0;
            for (int bb = 255; bb >= 0; bb--) {
                acc += (int)hist[bb];
                if (acc >= kneed) {
                    s_prefix = prefix | ((unsigned)bb << shift);
                    s_k = kneed - (acc - (int)hist[bb]);
                    break;
                }
            }
        }
        __syncthreads();
        prefix = s_prefix;
        kneed = s_k;
        __syncthreads();
    }
    const unsigned T = prefix;
    if (tid == 0) {
        int r = kneed;
        for (int i = 0; i < HH; i++) {
            if (__float_as_uint(fabsf(zrow[i])) == T) {
                if (r > 0) r--; else zrow[i] = 0.f;
            }
        }
    }
    __syncthreads();

    float sse = 0.f, sab = 0.f, saz = 0.f;
    for (int i = tid; i < HH; i += 256) {
        const float z  = zrow[i];
        const float zm = (__float_as_uint(fabsf(z)) >= T) ? z : 0.f;
        const float zv = zl[i];
        const float d  = zm - zv;
        sse += d * d;
        sab += fabsf(d);
        saz += fabsf(zm);
    }
    red[tid] = sse; __syncthreads();
    for (int s = 128; s; s >>= 1) { if (tid < s) red[tid] += red[tid + s]; __syncthreads(); }
    if (tid == 0) atomicAdd(&g_acc[3], (double)red[0]);
    __syncthreads();
    red[tid] = sab; __syncthreads();
    for (int s = 128; s; s >>= 1) { if (tid < s) red[tid] += red[tid + s]; __syncthreads(); }
    if (tid == 0) atomicAdd(&g_acc[4], (double)red[0]);
    __syncthreads();
    red[tid] = saz; __syncthreads();
    for (int s = 128; s; s >>= 1) { if (tid < s) red[tid] += red[tid + s]; __syncthreads(); }
    if (tid == 0) atomicAdd(&g_acc[5], (double)red[0]);
}

// ---------------------------------------------------------------------------
__global__ void k_final(float* __restrict__ out) {
    if (threadIdx.x == 0 && blockIdx.x == 0) {
        out[0] = (float)(g_acc[2] / ((double)BB * DD));
        out[1] = (float)(g_acc[3] / ((double)BB * HH));
        out[2] = (float)(g_acc[4] / ((double)BB * HH));
        out[3] = (float)(g_acc[0] / ((double)HH * HH));
        out[4] = (float)(g_acc[1] / ((double)HH * HH));
        out[5] = (float)(g_acc[5] / ((double)BB * HH));
    }
}

// ---------------------------------------------------------------------------
extern "C" void kernel_launch(void* const* d_in, const int* in_sizes, int n_in,
                              void* d_out, int out_size) {
    (void)in_sizes; (void)n_in; (void)out_size;
    const float* Xp  = (const float*)d_in[0];
    const float* Fe  = (const float*)d_in[1];
    const float* Fd  = (const float*)d_in[2];
    const float* Bsw = (const float*)d_in[3];
    const float* Mw  = (const float*)d_in[4];
    float* out = (float*)d_out;

    cudaFuncSetAttribute(k_zp_mma, cudaFuncAttributeMaxDynamicSharedMemorySize, SMEM_DYN);
    cudaFuncSetAttribute(k_zt_mma, cudaFuncAttributeMaxDynamicSharedMemorySize, SMEM_DYN);

    k_init<<<1, 32>>>();
    k_conv_x<<<(BB * DD + 255) / 256, 256>>>(Xp);
    k_conv_fe<<<dim3(DD / 32, HH / 32), dim3(32, 8)>>>(Fe);
    k_convB<<<2048, 256>>>(Bsw, Mw);

    k_zp_mma<<<dim3(HH / 128, BB / 128, TT), 256, SMEM_DYN>>>();
    k_zt_mma<<<dim3(HH / 128, BB / 128), 256, SMEM_DYN>>>();

    k_recons<<<dim3(DD / 64, BB / 64), 256>>>(Fd, Xp);
    k_topk<<<BB, 256>>>();
    k_final<<<1, 32>>>(out);
}

// round 8
// speedup vs baseline: 2.9683x; 1.1672x over previous
#include <cuda_runtime.h>
#include <cuda_bf16.h>
#include <cuda_fp16.h>
#include <cstdint>
#include <math.h>

// Problem constants
#define BB   512
#define DD   1024
#define HH   4096
#define TT   21
#define TAUV 20
#define KTOP 100
#define KTOT (TT * HH)        // 86016 = fused contraction length for k_zt
#define BK   32
#define SST  40               // smem k-stride in b16 units (80 B, ldmatrix-friendly)
#define TEN_BYTES (128 * SST * 2)     // 10240 B per tensor per stage
// k_zp (bf16, 4 tensors, 2 stages)
#define STAGE_BYTES (4 * TEN_BYTES)
#define SMEM_ZP (2 * STAGE_BYTES)     // 81920
// k_zt (fp16, 3 tensors, 3 stages)
#define STAGE2 (3 * TEN_BYTES)        // 30720
#define NST 3
#define SMEM_ZT (NST * STAGE2)        // 92160

// ---------------------------------------------------------------------------
// Static device scratch (no allocations allowed)
// ---------------------------------------------------------------------------
__device__ __nv_bfloat16 g_Xh[(size_t)TT * BB * DD];   // X hi  [t][b][d]
__device__ __nv_bfloat16 g_Xl[(size_t)TT * BB * DD];   // X lo
__device__ __nv_bfloat16 g_Feh[(size_t)HH * DD];       // F_enc^T hi [h][d]
__device__ __nv_bfloat16 g_Fel[(size_t)HH * DD];       // F_enc^T lo
__device__ __half g_A16[(size_t)BB * KTOT];            // Zp fp16 [b][layer*H+h']
__device__ __half g_Bh[(size_t)HH * KTOT];             // Bs/trilM fp16 hi [h][layer*H+d]
__device__ __half g_Bl[(size_t)HH * KTOT];             // Bs/trilM fp16 lo
__device__ float g_Zlast[(size_t)BB * HH];
__device__ float g_Zt   [(size_t)BB * HH];
// 0=sum|Bs| 1=sum|trilM| 2=sseX 3=sseZ 4=sumAbsE 5=sum|Zt|
__device__ double g_acc[8];

// ---------------------------------------------------------------------------
// PTX helpers (base-target only: cp.async / ldmatrix / mma.sync)
// ---------------------------------------------------------------------------
__device__ __forceinline__ uint32_t smem_u32(const void* p) {
    uint32_t a;
    asm("{ .reg .u64 t; cvta.to.shared.u64 t, %1; cvt.u32.u64 %0, t; }"
        : "=r"(a) : "l"(p));
    return a;
}
__device__ __forceinline__ void cp_async16(uint32_t saddr, const void* gaddr) {
    asm volatile("cp.async.cg.shared.global [%0], [%1], 16;"
                 :: "r"(saddr), "l"(gaddr) : "memory");
}
__device__ __forceinline__ void cp_commit() {
    asm volatile("cp.async.commit_group;" ::: "memory");
}
__device__ __forceinline__ void cp_wait2() {
    asm volatile("cp.async.wait_group 2;" ::: "memory");
}
__device__ __forceinline__ void cp_wait1() {
    asm volatile("cp.async.wait_group 1;" ::: "memory");
}
__device__ __forceinline__ void cp_wait0() {
    asm volatile("cp.async.wait_group 0;" ::: "memory");
}
__device__ __forceinline__ void ldsm_x4(uint32_t* r, uint32_t addr) {
    asm volatile("ldmatrix.sync.aligned.m8n8.x4.shared.b16 {%0,%1,%2,%3}, [%4];"
                 : "=r"(r[0]), "=r"(r[1]), "=r"(r[2]), "=r"(r[3]) : "r"(addr));
}
__device__ __forceinline__ void ldsm_x2(uint32_t* r, uint32_t addr) {
    asm volatile("ldmatrix.sync.aligned.m8n8.x2.shared.b16 {%0,%1}, [%2];"
                 : "=r"(r[0]), "=r"(r[1]) : "r"(addr));
}
__device__ __forceinline__ void mma_bf16(float* c, const uint32_t* a, const uint32_t* b) {
    asm volatile(
        "mma.sync.aligned.m16n8k16.row.col.f32.bf16.bf16.f32 "
        "{%0,%1,%2,%3}, {%4,%5,%6,%7}, {%8,%9}, {%0,%1,%2,%3};"
        : "+f"(c[0]), "+f"(c[1]), "+f"(c[2]), "+f"(c[3])
        : "r"(a[0]), "r"(a[1]), "r"(a[2]), "r"(a[3]), "r"(b[0]), "r"(b[1]));
}
__device__ __forceinline__ void mma_f16(float* c, const uint32_t* a, const uint32_t* b) {
    asm volatile(
        "mma.sync.aligned.m16n8k16.row.col.f32.f16.f16.f32 "
        "{%0,%1,%2,%3}, {%4,%5,%6,%7}, {%8,%9}, {%0,%1,%2,%3};"
        : "+f"(c[0]), "+f"(c[1]), "+f"(c[2]), "+f"(c[3])
        : "r"(a[0]), "r"(a[1]), "r"(a[2]), "r"(a[3]), "r"(b[0]), "r"(b[1]));
}

// ---------------------------------------------------------------------------
// bf16 3-term mainloop (used by k_zp): acc += Ah*Bh + Ah*Bl + Al*Bh.
// CTA 128x128, 8 warps (2m x 4n), warp tile 64x32, BK=32, 2-stage cp.async.
// ---------------------------------------------------------------------------
template <int KT>
__device__ __forceinline__ void mma_mainloop_bf16(
    const __nv_bfloat16* __restrict__ A_h, const __nv_bfloat16* __restrict__ A_l,
    const __nv_bfloat16* __restrict__ B_h, const __nv_bfloat16* __restrict__ B_l,
    char* smem, float acc[4][4][4])
{
    const int tid  = threadIdx.x;
    const int lane = tid & 31, warp = tid >> 5;
    const int wm = warp & 1, wn = warp >> 1;
    const uint32_t sbase = smem_u32(smem);

    const int lrow = tid >> 1;
    const int lk   = (tid & 1) * 16;
    const size_t grow = (size_t)lrow * KT + lk;
    constexpr int NKT = KT / BK;

    auto issue_stage = [&](int kt, int s) {
        const size_t kb = grow + (size_t)kt * BK;
        const uint32_t so = sbase + s * STAGE_BYTES + (lrow * SST + lk) * 2;
        cp_async16(so + 0 * TEN_BYTES,      A_h + kb);
        cp_async16(so + 0 * TEN_BYTES + 16, A_h + kb + 8);
        cp_async16(so + 1 * TEN_BYTES,      A_l + kb);
        cp_async16(so + 1 * TEN_BYTES + 16, A_l + kb + 8);
        cp_async16(so + 2 * TEN_BYTES,      B_h + kb);
        cp_async16(so + 2 * TEN_BYTES + 16, B_h + kb + 8);
        cp_async16(so + 3 * TEN_BYTES,      B_l + kb);
        cp_async16(so + 3 * TEN_BYTES + 16, B_l + kb + 8);
    };

    const int arow = lane & 15;
    const int akc  = (lane >> 4) * 8;
    const int brow = lane & 7;
    const int bkc  = ((lane >> 3) & 1) * 8;

    issue_stage(0, 0);
    cp_commit();

    for (int kt = 0; kt < NKT; kt++) {
        const int s = kt & 1;
        if (kt + 1 < NKT) { issue_stage(kt + 1, s ^ 1); cp_commit(); cp_wait1(); }
        else              { cp_wait0(); }
        __syncthreads();

        const uint32_t tb = sbase + s * STAGE_BYTES;
#pragma unroll
        for (int kk = 0; kk < 2; kk++) {
            uint32_t ah[4][4], al[4][4], bh[4][2], bl[4][2];
#pragma unroll
            for (int mi = 0; mi < 4; mi++) {
                const uint32_t ad = tb +
                    ((wm * 64 + mi * 16 + arow) * SST + kk * 16 + akc) * 2;
                ldsm_x4(ah[mi], ad);
                ldsm_x4(al[mi], ad + TEN_BYTES);
            }
#pragma unroll
            for (int ni = 0; ni < 4; ni++) {
                const uint32_t bd = tb + 2 * TEN_BYTES +
                    ((wn * 32 + ni * 8 + brow) * SST + kk * 16 + bkc) * 2;
                ldsm_x2(bh[ni], bd);
                ldsm_x2(bl[ni], bd + TEN_BYTES);
            }
#pragma unroll
            for (int mi = 0; mi < 4; mi++)
#pragma unroll
                for (int ni = 0; ni < 4; ni++) {
                    mma_bf16(acc[mi][ni], ah[mi], bh[ni]);
                    mma_bf16(acc[mi][ni], ah[mi], bl[ni]);
                    mma_bf16(acc[mi][ni], al[mi], bh[ni]);
                }
        }
        __syncthreads();
    }
}

// ---------------------------------------------------------------------------
__global__ void k_init() {
    if (threadIdx.x < 8) g_acc[threadIdx.x] = 0.0;
}

// Xp (B,D,T) t-fastest  ->  bf16 hi/lo [t][b][d]
__global__ void k_conv_x(const float* __restrict__ Xp) {
    int idx = blockIdx.x * blockDim.x + threadIdx.x;
    if (idx >= BB * DD) return;
    const float* s = Xp + (size_t)idx * TT;
#pragma unroll
    for (int t = 0; t < TT; t++) {
        const float v = s[t];
        const __nv_bfloat16 h = __float2bfloat16_rn(v);
        const __nv_bfloat16 l = __float2bfloat16_rn(v - __bfloat162float(h));
        g_Xh[(size_t)t * BB * DD + idx] = h;
        g_Xl[(size_t)t * BB * DD + idx] = l;
    }
}

// F_enc (D,H) -> transposed bf16 hi/lo [h][d]
__global__ void k_conv_fe(const float* __restrict__ Fe) {
    __shared__ float tile[32][33];
    const int d0 = blockIdx.x * 32, h0 = blockIdx.y * 32;
    for (int r = threadIdx.y; r < 32; r += 8)
        tile[r][threadIdx.x] = Fe[(size_t)(d0 + r) * HH + h0 + threadIdx.x];
    __syncthreads();
    for (int r = threadIdx.y; r < 32; r += 8) {
        const float v = tile[threadIdx.x][r];
        const __nv_bfloat16 h = __float2bfloat16_rn(v);
        const __nv_bfloat16 l = __float2bfloat16_rn(v - __bfloat162float(h));
        const size_t o = (size_t)(h0 + r) * DD + d0 + threadIdx.x;
        g_Feh[o] = h;
        g_Fel[o] = l;
    }
}

// Bs (20,H,H) + tril(M,1) -> fp16 hi/lo [h][layer*H+d], fused |Bs| / |M| sums
__global__ void __launch_bounds__(256) k_convB(const float* __restrict__ Bsw,
                                               const float* __restrict__ Mw) {
    __shared__ float red[256];
    const size_t total = (size_t)TT * HH * (HH / 4);   // float4 units
    float sBs = 0.f, sM = 0.f;
    for (size_t u = blockIdx.x * 256 + threadIdx.x; u < total;
         u += (size_t)gridDim.x * 256) {
        const int d4 = (int)(u & 1023);
        const int h  = (int)((u >> 10) & 4095);
        const int l  = (int)(u >> 22);
        float4 v;
        if (l < TAUV) {
            v = *(const float4*)(Bsw + (((size_t)l * HH + h) * HH + d4 * 4));
            sBs += fabsf(v.x) + fabsf(v.y) + fabsf(v.z) + fabsf(v.w);
        } else {
            v = *(const float4*)(Mw + ((size_t)h * HH + d4 * 4));
            float* e = (float*)&v;
#pragma unroll
            for (int j = 0; j < 4; j++)
                if (d4 * 4 + j > h + 1) e[j] = 0.f;
            sM += fabsf(v.x) + fabsf(v.y) + fabsf(v.z) + fabsf(v.w);
        }
        const __half h0 = __float2half_rn(v.x), h1 = __float2half_rn(v.y);
        const __half h2 = __float2half_rn(v.z), h3 = __float2half_rn(v.w);
        const __half l0 = __float2half_rn(v.x - __half2float(h0));
        const __half l1 = __float2half_rn(v.y - __half2float(h1));
        const __half l2 = __float2half_rn(v.z - __half2float(h2));
        const __half l3 = __float2half_rn(v.w - __half2float(h3));
        const size_t o = (size_t)h * KTOT + (size_t)l * HH + d4 * 4;
        union { __half2 b; uint32_t u; } p0, p1, q0, q1;
        p0.b = __halves2half2(h0, h1); p1.b = __halves2half2(h2, h3);
        q0.b = __halves2half2(l0, l1); q1.b = __halves2half2(l2, l3);
        *(uint2*)(g_Bh + o) = make_uint2(p0.u, p1.u);
        *(uint2*)(g_Bl + o) = make_uint2(q0.u, q1.u);
    }
    const int tid = threadIdx.x;
    red[tid] = sBs; __syncthreads();
    for (int s = 128; s; s >>= 1) { if (tid < s) red[tid] += red[tid + s]; __syncthreads(); }
    if (tid == 0) atomicAdd(&g_acc[0], (double)red[0]);
    __syncthreads();
    red[tid] = sM; __syncthreads();
    for (int s = 128; s; s >>= 1) { if (tid < s) red[tid] += red[tid + s]; __syncthreads(); }
    if (tid == 0) atomicAdd(&g_acc[1], (double)red[0]);
}

// ---------------------------------------------------------------------------
// GEMM 1 (bf16 3-term): Zp[t] = X[t] (B x D) @ F_enc^T (H x D)^T.
// Epilogue: fp16 Zp into the k_zt A layout (flip baked in) + fp32 Z_last.
// ---------------------------------------------------------------------------
__global__ void __launch_bounds__(256, 1) k_zp_mma() {
    extern __shared__ char smem[];
    const int tid = threadIdx.x;
    const int lane = tid & 31, warp = tid >> 5;
    const int wm = warp & 1, wn = warp >> 1;
    const int t = blockIdx.z;
    const int m0 = blockIdx.y * 128, n0 = blockIdx.x * 128;

    float acc[4][4][4] = {};
    mma_mainloop_bf16<DD>(g_Xh + ((size_t)t * BB + m0) * DD,
                          g_Xl + ((size_t)t * BB + m0) * DD,
                          g_Feh + (size_t)n0 * DD,
                          g_Fel + (size_t)n0 * DD,
                          smem, acc);

    const int layer = (t < TAUV) ? (TAUV - 1 - t) : TAUV;
    const int mb = m0 + wm * 64 + (lane >> 2);
    const int nb = n0 + wn * 32 + (lane & 3) * 2;
#pragma unroll
    for (int mi = 0; mi < 4; mi++)
#pragma unroll
        for (int ni = 0; ni < 4; ni++)
#pragma unroll
            for (int half = 0; half < 2; half++) {
                const int m = mb + mi * 16 + half * 8;
                const int n = nb + ni * 8;
                const float f0 = acc[mi][ni][half * 2];
                const float f1 = acc[mi][ni][half * 2 + 1];
                const size_t o = (size_t)m * KTOT + (size_t)layer * HH + n;
                *(__half2*)(g_A16 + o) = __floats2half2_rn(f0, f1);
                if (t == TAUV)
                    *(float2*)(g_Zlast + (size_t)m * HH + n) = make_float2(f0, f1);
            }
}

// ---------------------------------------------------------------------------
// GEMM 2 (fp16 2-term, fused): Zt (B x H) over K = 21*4096.
//   acc += A*Bh + A*Bl,  A = fp16(Zp), B = fp16 hi/lo of Bs/tril(M,1).
// 3-stage cp.async pipeline; B loaded via paired ldmatrix.x4.
// ---------------------------------------------------------------------------
__global__ void __launch_bounds__(256, 1) k_zt_f16() {
    extern __shared__ char smem[];
    const int tid = threadIdx.x;
    const int lane = tid & 31, warp = tid >> 5;
    const int wm = warp & 1, wn = warp >> 1;
    const int m0 = blockIdx.y * 128, n0 = blockIdx.x * 128;
    const uint32_t sbase = smem_u32(smem);

    const __half* A  = g_A16 + (size_t)m0 * KTOT;
    const __half* Bh = g_Bh + (size_t)n0 * KTOT;
    const __half* Bl = g_Bl + (size_t)n0 * KTOT;

    const int lrow = tid >> 1, lk = (tid & 1) * 16;
    const size_t grow = (size_t)lrow * KTOT + lk;
    constexpr int NKT = KTOT / BK;   // 2688

    auto issue = [&](int kt) {
        const int s = kt % NST;
        const size_t kb = grow + (size_t)kt * BK;
        const uint32_t so = sbase + s * STAGE2 + (lrow * SST + lk) * 2;
        cp_async16(so,                      A + kb);
        cp_async16(so + 16,                 A + kb + 8);
        cp_async16(so + TEN_BYTES,          Bh + kb);
        cp_async16(so + TEN_BYTES + 16,     Bh + kb + 8);
        cp_async16(so + 2 * TEN_BYTES,      Bl + kb);
        cp_async16(so + 2 * TEN_BYTES + 16, Bl + kb + 8);
        cp_commit();
    };

    float acc[4][4][4] = {};
    issue(0); issue(1);

    const int arow = lane & 15, akc = (lane >> 4) * 8;
    const int brow = lane & 15, bkc = (lane >> 4) * 8;

    for (int kt = 0; kt < NKT; kt++) {
        if (kt + 2 < NKT)      { issue(kt + 2); cp_wait2(); }
        else if (kt + 1 < NKT) cp_wait1();
        else                   cp_wait0();
        __syncthreads();

        const uint32_t tb = sbase + (kt % NST) * STAGE2;
#pragma unroll
        for (int kk = 0; kk < 2; kk++) {
            uint32_t a[4][4], bh[4][2], bl[4][2];
#pragma unroll
            for (int mi = 0; mi < 4; mi++)
                ldsm_x4(a[mi], tb + ((wm * 64 + mi * 16 + arow) * SST + kk * 16 + akc) * 2);
#pragma unroll
            for (int p = 0; p < 2; p++) {
                uint32_t r[4];
                const uint32_t bd = tb + TEN_BYTES +
                    ((wn * 32 + p * 16 + brow) * SST + kk * 16 + bkc) * 2;
                ldsm_x4(r, bd);
                bh[2 * p][0] = r[0]; bh[2 * p][1] = r[2];
                bh[2 * p + 1][0] = r[1]; bh[2 * p + 1][1] = r[3];
                ldsm_x4(r, bd + TEN_BYTES);
                bl[2 * p][0] = r[0]; bl[2 * p][1] = r[2];
                bl[2 * p + 1][0] = r[1]; bl[2 * p + 1][1] = r[3];
            }
#pragma unroll
            for (int mi = 0; mi < 4; mi++)
#pragma unroll
                for (int ni = 0; ni < 4; ni++) {
                    mma_f16(acc[mi][ni], a[mi], bh[ni]);
                    mma_f16(acc[mi][ni], a[mi], bl[ni]);
                }
        }
        __syncthreads();
    }

    const int mb = m0 + wm * 64 + (lane >> 2);
    const int nb = n0 + wn * 32 + (lane & 3) * 2;
#pragma unroll
    for (int mi = 0; mi < 4; mi++)
#pragma unroll
        for (int ni = 0; ni < 4; ni++)
#pragma unroll
            for (int half = 0; half < 2; half++) {
                const int m = mb + mi * 16 + half * 8;
                const int n = nb + ni * 8;
                *(float2*)(g_Zt + (size_t)m * HH + n) =
                    make_float2(acc[mi][ni][half * 2], acc[mi][ni][half * 2 + 1]);
            }
}

// ---------------------------------------------------------------------------
// GEMM 3 (SIMT fp32) + fused MSE: recons = Z_last (B x H) @ F_dec (H x D)
// ---------------------------------------------------------------------------
__global__ void __launch_bounds__(256) k_recons(const float* __restrict__ Fd,
                                                const float* __restrict__ Xp) {
    __shared__ float Asb[16][68];
    __shared__ float Bsb[16][68];
    __shared__ float red[256];

    const float* A = g_Zlast;
    const int tid = threadIdx.x;
    const int tx = tid & 15, ty = tid >> 4;
    const int m0 = blockIdx.y * 64, n0 = blockIdx.x * 64;
    const int arow = tid >> 2, akq = tid & 3;
    const int brow = tid >> 4, bq  = tid & 15;

    float acc[4][4] = {};

    for (int k0 = 0; k0 < HH; k0 += 16) {
        float4 av = *(const float4*)(A + (size_t)(m0 + arow) * HH + k0 + akq * 4);
        Asb[akq * 4 + 0][arow] = av.x;
        Asb[akq * 4 + 1][arow] = av.y;
        Asb[akq * 4 + 2][arow] = av.z;
        Asb[akq * 4 + 3][arow] = av.w;
        float4 bv = *(const float4*)(Fd + (size_t)(k0 + brow) * DD + n0 + bq * 4);
        *(float4*)&Bsb[brow][bq * 4] = bv;
        __syncthreads();
#pragma unroll
        for (int kk = 0; kk < 16; kk++) {
            const float4 a4 = *(const float4*)&Asb[kk][ty * 4];
            const float4 b4 = *(const float4*)&Bsb[kk][tx * 4];
            const float ar[4] = {a4.x, a4.y, a4.z, a4.w};
            const float br[4] = {b4.x, b4.y, b4.z, b4.w};
#pragma unroll
            for (int i = 0; i < 4; i++)
#pragma unroll
                for (int j = 0; j < 4; j++)
                    acc[i][j] += ar[i] * br[j];
        }
        __syncthreads();
    }
    float sse = 0.f;
#pragma unroll
    for (int i = 0; i < 4; i++)
#pragma unroll
        for (int j = 0; j < 4; j++) {
            const int b = m0 + ty * 4 + i;
            const int d = n0 + tx * 4 + j;
            const float x = Xp[((size_t)b * DD + d) * TT + TAUV];
            const float df = acc[i][j] - x;
            sse += df * df;
        }
    red[tid] = sse; __syncthreads();
    for (int s = 128; s; s >>= 1) { if (tid < s) red[tid] += red[tid + s]; __syncthreads(); }
    if (tid == 0) atomicAdd(&g_acc[2], (double)red[0]);
}

// ---------------------------------------------------------------------------
// Per-row exact top-100 via 8-bit radix select on |Zt|, then masked losses.
// ---------------------------------------------------------------------------
__global__ void __launch_bounds__(256) k_topk() {
    __shared__ float    zrow[HH];
    __shared__ unsigned hist[256];
    __shared__ unsigned s_prefix;
    __shared__ int      s_k;
    __shared__ float    red[256];

    const int b = blockIdx.x, tid = threadIdx.x;
    const float* zt = g_Zt + (size_t)b * HH;
    const float* zl = g_Zlast + (size_t)b * HH;

    for (int i = tid; i < HH; i += 256) zrow[i] = zt[i];
    __syncthreads();

    unsigned prefix = 0u;
    int kneed = KTOP;
    for (int shift = 24; shift >= 0; shift -= 8) {
        hist[tid] = 0u;
        __syncthreads();
        const unsigned hm = (shift == 24) ? 0u : (0xFFFFFFFFu << (shift + 8));
        for (int i = tid; i < HH; i += 256) {
            const unsigned bits = __float_as_uint(fabsf(zrow[i]));
            if ((bits & hm) == prefix) atomicAdd(&hist[(bits >> shift) & 255u], 1u);
        }
        __syncthreads();
        if (tid == 0) {
            int acc = 0;
            for (int bb = 255; bb >= 0; bb--) {
                acc += (int)hist[bb];
                if (acc >= kneed) {
                    s_prefix = prefix | ((unsigned)bb << shift);
                    s_k = kneed - (acc - (int)hist[bb]);
                    break;
                }
            }
        }
        __syncthreads();
        prefix = s_prefix;
        kneed = s_k;
        __syncthreads();
    }
    const unsigned T = prefix;
    if (tid == 0) {
        int r = kneed;
        for (int i = 0; i < HH; i++) {
            if (__float_as_uint(fabsf(zrow[i])) == T) {
                if (r > 0) r--; else zrow[i] = 0.f;
            }
        }
    }
    __syncthreads();

    float sse = 0.f, sab = 0.f, saz = 0.f;
    for (int i = tid; i < HH; i += 256) {
        const float z  = zrow[i];
        const float zm = (__float_as_uint(fabsf(z)) >= T) ? z : 0.f;
        const float zv = zl[i];
        const float d  = zm - zv;
        sse += d * d;
        sab += fabsf(d);
        saz += fabsf(zm);
    }
    red[tid] = sse; __syncthreads();
    for (int s = 128; s; s >>= 1) { if (tid < s) red[tid] += red[tid + s]; __syncthreads(); }
    if (tid == 0) atomicAdd(&g_acc[3], (double)red[0]);
    __syncthreads();
    red[tid] = sab; __syncthreads();
    for (int s = 128; s; s >>= 1) { if (tid < s) red[tid] += red[tid + s]; __syncthreads(); }
    if (tid == 0) atomicAdd(&g_acc[4], (double)red[0]);
    __syncthreads();
    red[tid] = saz; __syncthreads();
    for (int s = 128; s; s >>= 1) { if (tid < s) red[tid] += red[tid + s]; __syncthreads(); }
    if (tid == 0) atomicAdd(&g_acc[5], (double)red[0]);
}

// ---------------------------------------------------------------------------
__global__ void k_final(float* __restrict__ out) {
    if (threadIdx.x == 0 && blockIdx.x == 0) {
        out[0] = (float)(g_acc[2] / ((double)BB * DD));
        out[1] = (float)(g_acc[3] / ((double)BB * HH));
        out[2] = (float)(g_acc[4] / ((double)BB * HH));
        out[3] = (float)(g_acc[0] / ((double)HH * HH));
        out[4] = (float)(g_acc[1] / ((double)HH * HH));
        out[5] = (float)(g_acc[5] / ((double)BB * HH));
    }
}

// ---------------------------------------------------------------------------
extern "C" void kernel_launch(void* const* d_in, const int* in_sizes, int n_in,
                              void* d_out, int out_size) {
    (void)in_sizes; (void)n_in; (void)out_size;
    const float* Xp  = (const float*)d_in[0];
    const float* Fe  = (const float*)d_in[1];
    const float* Fd  = (const float*)d_in[2];
    const float* Bsw = (const float*)d_in[3];
    const float* Mw  = (const float*)d_in[4];
    float* out = (float*)d_out;

    cudaFuncSetAttribute(k_zp_mma, cudaFuncAttributeMaxDynamicSharedMemorySize, SMEM_ZP);
    cudaFuncSetAttribute(k_zt_f16, cudaFuncAttributeMaxDynamicSharedMemorySize, SMEM_ZT);

    k_init<<<1, 32>>>();
    k_conv_x<<<(BB * DD + 255) / 256, 256>>>(Xp);
    k_conv_fe<<<dim3(DD / 32, HH / 32), dim3(32, 8)>>>(Fe);
    k_convB<<<2048, 256>>>(Bsw, Mw);

    k_zp_mma<<<dim3(HH / 128, BB / 128, TT), 256, SMEM_ZP>>>();
    k_zt_f16<<<dim3(HH / 128, BB / 128), 256, SMEM_ZT>>>();

    k_recons<<<dim3(DD / 64, BB / 64), 256>>>(Fd, Xp);
    k_topk<<<BB, 256>>>();
    k_final<<<1, 32>>>(out);
}

// round 9
// speedup vs baseline: 4.7264x; 1.5923x over previous
#include <cuda_runtime.h>
#include <cuda_fp16.h>
#include <cstdint>
#include <math.h>

// Problem constants
#define BB   512
#define DD   1024
#define HH   4096
#define TT   21
#define TAUV 20
#define KTOP 100
#define KTOT (TT * HH)        // 86016 = fused contraction length for k_zt
#define BK   32
#define SST  40               // smem k-stride in halves (80 B, ldmatrix-friendly)
#define TEN_BYTES (128 * SST * 2)     // 10240 B per tensor per stage
#define STG  (2 * TEN_BYTES)          // A|B per stage = 20480
#define NST  4
#define SMEM_MMA (NST * STG)          // 81920

// ---------------------------------------------------------------------------
// Static device scratch (no allocations allowed)
// ---------------------------------------------------------------------------
__device__ __half g_X16[(size_t)TT * BB * DD];   // X fp16 [t][b][d]
__device__ float  g_X20[(size_t)BB * DD];        // X[:,:,20] fp32 compact
__device__ __half g_Fe16[(size_t)HH * DD];       // F_enc^T fp16 [h][d]
__device__ __half g_A16[(size_t)BB * KTOT];      // Zp fp16 [b][layer*H+h']
__device__ __half g_B16[(size_t)HH * KTOT];      // Bs/trilM fp16 [h][layer*H+d]
__device__ float g_Zlast[(size_t)BB * HH];       // exact fp32 Z_last
__device__ float g_Zt   [(size_t)BB * HH];
// 0=sum|Bs| 1=sum|trilM| 2=sseX 3=sseZ 4=sumAbsE 5=sum|Zt|
__device__ double g_acc[8];

// ---------------------------------------------------------------------------
// PTX helpers (base-target only: cp.async / ldmatrix / mma.sync)
// ---------------------------------------------------------------------------
__device__ __forceinline__ uint32_t smem_u32(const void* p) {
    uint32_t a;
    asm("{ .reg .u64 t; cvta.to.shared.u64 t, %1; cvt.u32.u64 %0, t; }"
        : "=r"(a) : "l"(p));
    return a;
}
__device__ __forceinline__ void cp_async16(uint32_t saddr, const void* gaddr) {
    asm volatile("cp.async.cg.shared.global [%0], [%1], 16;"
                 :: "r"(saddr), "l"(gaddr) : "memory");
}
__device__ __forceinline__ void cp_commit() {
    asm volatile("cp.async.commit_group;" ::: "memory");
}
__device__ __forceinline__ void cp_wait3() {
    asm volatile("cp.async.wait_group 3;" ::: "memory");
}
__device__ __forceinline__ void cp_wait2() {
    asm volatile("cp.async.wait_group 2;" ::: "memory");
}
__device__ __forceinline__ void cp_wait1() {
    asm volatile("cp.async.wait_group 1;" ::: "memory");
}
__device__ __forceinline__ void cp_wait0() {
    asm volatile("cp.async.wait_group 0;" ::: "memory");
}
__device__ __forceinline__ void ldsm_x4(uint32_t* r, uint32_t addr) {
    asm volatile("ldmatrix.sync.aligned.m8n8.x4.shared.b16 {%0,%1,%2,%3}, [%4];"
                 : "=r"(r[0]), "=r"(r[1]), "=r"(r[2]), "=r"(r[3]) : "r"(addr));
}
__device__ __forceinline__ void mma_f16(float* c, const uint32_t* a, const uint32_t* b) {
    asm volatile(
        "mma.sync.aligned.m16n8k16.row.col.f32.f16.f16.f32 "
        "{%0,%1,%2,%3}, {%4,%5,%6,%7}, {%8,%9}, {%0,%1,%2,%3};"
        : "+f"(c[0]), "+f"(c[1]), "+f"(c[2]), "+f"(c[3])
        : "r"(a[0]), "r"(a[1]), "r"(a[2]), "r"(a[3]), "r"(b[0]), "r"(b[1]));
}

// ---------------------------------------------------------------------------
// fp16 1-term mainloop: acc += A*B over K = KT.
// CTA 128x128, 8 warps (2m x 4n), warp tile 64x32, BK=32, 4-stage cp.async.
// A: [128 m-rows][KT] k-contig.  B: [128 n-rows][KT] k-contig.
// ---------------------------------------------------------------------------
template <int KT>
__device__ __forceinline__ void mma_mainloop_f16(
    const __half* __restrict__ A, const __half* __restrict__ B,
    char* smem, float acc[4][4][4])
{
    const int tid  = threadIdx.x;
    const int lane = tid & 31, warp = tid >> 5;
    const int wm = warp & 1, wn = warp >> 1;
    const uint32_t sbase = smem_u32(smem);

    const int lrow = tid >> 1;
    const int lk   = (tid & 1) * 16;
    const size_t grow = (size_t)lrow * KT + lk;
    constexpr int NKT = KT / BK;

    auto issue = [&](int kt) {
        const int s = kt & (NST - 1);
        const size_t kb = grow + (size_t)kt * BK;
        const uint32_t so = sbase + s * STG + (lrow * SST + lk) * 2;
        cp_async16(so,                  A + kb);
        cp_async16(so + 16,             A + kb + 8);
        cp_async16(so + TEN_BYTES,      B + kb);
        cp_async16(so + TEN_BYTES + 16, B + kb + 8);
        cp_commit();
    };

    issue(0); issue(1); issue(2);

    const int arow = lane & 15, akc = (lane >> 4) * 8;
    const int brow = lane & 15, bkc = (lane >> 4) * 8;

    for (int kt = 0; kt < NKT; kt++) {
        if (kt + 3 < NKT)      { issue(kt + 3); cp_wait3(); }
        else if (kt + 2 < NKT) cp_wait2();
        else if (kt + 1 < NKT) cp_wait1();
        else                   cp_wait0();
        __syncthreads();

        const uint32_t tb = sbase + (kt & (NST - 1)) * STG;
#pragma unroll
        for (int kk = 0; kk < 2; kk++) {
            uint32_t a[4][4], bh[4][2];
#pragma unroll
            for (int mi = 0; mi < 4; mi++)
                ldsm_x4(a[mi], tb + ((wm * 64 + mi * 16 + arow) * SST + kk * 16 + akc) * 2);
#pragma unroll
            for (int p = 0; p < 2; p++) {
                uint32_t r[4];
                ldsm_x4(r, tb + TEN_BYTES +
                        ((wn * 32 + p * 16 + brow) * SST + kk * 16 + bkc) * 2);
                bh[2 * p][0] = r[0];     bh[2 * p][1] = r[2];
                bh[2 * p + 1][0] = r[1]; bh[2 * p + 1][1] = r[3];
            }
#pragma unroll
            for (int mi = 0; mi < 4; mi++)
#pragma unroll
                for (int ni = 0; ni < 4; ni++)
                    mma_f16(acc[mi][ni], a[mi], bh[ni]);
        }
        __syncthreads();
    }
}

// ---------------------------------------------------------------------------
__global__ void k_init() {
    if (threadIdx.x < 8) g_acc[threadIdx.x] = 0.0;
}

// Xp (B,D,T) t-fastest -> fp16 [t][b][d] + fp32 X20 [b][d]
__global__ void k_conv_x(const float* __restrict__ Xp) {
    int idx = blockIdx.x * blockDim.x + threadIdx.x;
    if (idx >= BB * DD) return;
    const float* s = Xp + (size_t)idx * TT;
#pragma unroll
    for (int t = 0; t < TT; t++) {
        const float v = s[t];
        g_X16[(size_t)t * BB * DD + idx] = __float2half_rn(v);
        if (t == TAUV) g_X20[idx] = v;
    }
}

// F_enc (D,H) -> transposed fp16 [h][d]
__global__ void k_conv_fe(const float* __restrict__ Fe) {
    __shared__ float tile[32][33];
    const int d0 = blockIdx.x * 32, h0 = blockIdx.y * 32;
    for (int r = threadIdx.y; r < 32; r += 8)
        tile[r][threadIdx.x] = Fe[(size_t)(d0 + r) * HH + h0 + threadIdx.x];
    __syncthreads();
    for (int r = threadIdx.y; r < 32; r += 8)
        g_Fe16[(size_t)(h0 + r) * DD + d0 + threadIdx.x] =
            __float2half_rn(tile[threadIdx.x][r]);
}

// Bs (20,H,H) + tril(M,1) -> fp16 [h][layer*H+d], fused |Bs| / |M| sums
__global__ void __launch_bounds__(256) k_convB(const float* __restrict__ Bsw,
                                               const float* __restrict__ Mw) {
    __shared__ float red[256];
    const size_t total = (size_t)TT * HH * (HH / 4);   // float4 units
    float sBs = 0.f, sM = 0.f;
    for (size_t u = blockIdx.x * 256 + threadIdx.x; u < total;
         u += (size_t)gridDim.x * 256) {
        const int d4 = (int)(u & 1023);
        const int h  = (int)((u >> 10) & 4095);
        const int l  = (int)(u >> 22);
        float4 v;
        if (l < TAUV) {
            v = *(const float4*)(Bsw + (((size_t)l * HH + h) * HH + d4 * 4));
            sBs += fabsf(v.x) + fabsf(v.y) + fabsf(v.z) + fabsf(v.w);
        } else {
            v = *(const float4*)(Mw + ((size_t)h * HH + d4 * 4));
            float* e = (float*)&v;
#pragma unroll
            for (int j = 0; j < 4; j++)
                if (d4 * 4 + j > h + 1) e[j] = 0.f;
            sM += fabsf(v.x) + fabsf(v.y) + fabsf(v.z) + fabsf(v.w);
        }
        union { __half2 b; uint32_t u; } p0, p1;
        p0.b = __floats2half2_rn(v.x, v.y);
        p1.b = __floats2half2_rn(v.z, v.w);
        *(uint2*)(g_B16 + (size_t)h * KTOT + (size_t)l * HH + d4 * 4) =
            make_uint2(p0.u, p1.u);
    }
    const int tid = threadIdx.x;
    red[tid] = sBs; __syncthreads();
    for (int s = 128; s; s >>= 1) { if (tid < s) red[tid] += red[tid + s]; __syncthreads(); }
    if (tid == 0) atomicAdd(&g_acc[0], (double)red[0]);
    __syncthreads();
    red[tid] = sM; __syncthreads();
    for (int s = 128; s; s >>= 1) { if (tid < s) red[tid] += red[tid + s]; __syncthreads(); }
    if (tid == 0) atomicAdd(&g_acc[1], (double)red[0]);
}

// ---------------------------------------------------------------------------
// GEMM 1 (fp16 1-term): Zp[t] = X[t] (B x D) @ F_enc^T (H x D)^T.
// Epilogue: fp16 Zp into the k_zt A layout (flip baked in).
// ---------------------------------------------------------------------------
__global__ void __launch_bounds__(256, 1) k_zp_mma() {
    extern __shared__ char smem[];
    const int tid = threadIdx.x;
    const int lane = tid & 31, warp = tid >> 5;
    const int wm = warp & 1, wn = warp >> 1;
    const int t = blockIdx.z;
    const int m0 = blockIdx.y * 128, n0 = blockIdx.x * 128;

    float acc[4][4][4] = {};
    mma_mainloop_f16<DD>(g_X16 + ((size_t)t * BB + m0) * DD,
                         g_Fe16 + (size_t)n0 * DD,
                         smem, acc);

    const int layer = (t < TAUV) ? (TAUV - 1 - t) : TAUV;
    const int mb = m0 + wm * 64 + (lane >> 2);
    const int nb = n0 + wn * 32 + (lane & 3) * 2;
#pragma unroll
    for (int mi = 0; mi < 4; mi++)
#pragma unroll
        for (int ni = 0; ni < 4; ni++)
#pragma unroll
            for (int half = 0; half < 2; half++) {
                const int m = mb + mi * 16 + half * 8;
                const int n = nb + ni * 8;
                const size_t o = (size_t)m * KTOT + (size_t)layer * HH + n;
                *(__half2*)(g_A16 + o) =
                    __floats2half2_rn(acc[mi][ni][half * 2], acc[mi][ni][half * 2 + 1]);
            }
}

// ---------------------------------------------------------------------------
// GEMM 2 (fp16 1-term, fused): Zt (B x H) over K = 21*4096.
// ---------------------------------------------------------------------------
__global__ void __launch_bounds__(256, 1) k_zt_f16() {
    extern __shared__ char smem[];
    const int tid = threadIdx.x;
    const int lane = tid & 31, warp = tid >> 5;
    const int wm = warp & 1, wn = warp >> 1;
    const int m0 = blockIdx.y * 128, n0 = blockIdx.x * 128;

    float acc[4][4][4] = {};
    mma_mainloop_f16<KTOT>(g_A16 + (size_t)m0 * KTOT,
                           g_B16 + (size_t)n0 * KTOT,
                           smem, acc);

    const int mb = m0 + wm * 64 + (lane >> 2);
    const int nb = n0 + wn * 32 + (lane & 3) * 2;
#pragma unroll
    for (int mi = 0; mi < 4; mi++)
#pragma unroll
        for (int ni = 0; ni < 4; ni++)
#pragma unroll
            for (int half = 0; half < 2; half++) {
                const int m = mb + mi * 16 + half * 8;
                const int n = nb + ni * 8;
                *(float2*)(g_Zt + (size_t)m * HH + n) =
                    make_float2(acc[mi][ni][half * 2], acc[mi][ni][half * 2 + 1]);
            }
}

// ---------------------------------------------------------------------------
// Z_last exact (SIMT fp32, NN): Zlast = X20 (B x D) @ F_enc (D x H).
// 64x64 tile, 4x4 microtile. Only 4.3 GFLOP.
// ---------------------------------------------------------------------------
__global__ void __launch_bounds__(256) k_zlast(const float* __restrict__ Fe) {
    __shared__ float Asb[16][68];
    __shared__ float Bsb[16][68];

    const int tid = threadIdx.x;
    const int tx = tid & 15, ty = tid >> 4;
    const int m0 = blockIdx.y * 64, n0 = blockIdx.x * 64;
    const int arow = tid >> 2, akq = tid & 3;
    const int brow = tid >> 4, bq  = tid & 15;

    float acc[4][4] = {};

    for (int k0 = 0; k0 < DD; k0 += 16) {
        float4 av = *(const float4*)(g_X20 + (size_t)(m0 + arow) * DD + k0 + akq * 4);
        Asb[akq * 4 + 0][arow] = av.x;
        Asb[akq * 4 + 1][arow] = av.y;
        Asb[akq * 4 + 2][arow] = av.z;
        Asb[akq * 4 + 3][arow] = av.w;
        float4 bv = *(const float4*)(Fe + (size_t)(k0 + brow) * HH + n0 + bq * 4);
        *(float4*)&Bsb[brow][bq * 4] = bv;
        __syncthreads();
#pragma unroll
        for (int kk = 0; kk < 16; kk++) {
            const float4 a4 = *(const float4*)&Asb[kk][ty * 4];
            const float4 b4 = *(const float4*)&Bsb[kk][tx * 4];
            const float ar[4] = {a4.x, a4.y, a4.z, a4.w};
            const float br[4] = {b4.x, b4.y, b4.z, b4.w};
#pragma unroll
            for (int i = 0; i < 4; i++)
#pragma unroll
                for (int j = 0; j < 4; j++)
                    acc[i][j] += ar[i] * br[j];
        }
        __syncthreads();
    }
#pragma unroll
    for (int i = 0; i < 4; i++)
        *(float4*)(g_Zlast + (size_t)(m0 + ty * 4 + i) * HH + n0 + tx * 4) =
            make_float4(acc[i][0], acc[i][1], acc[i][2], acc[i][3]);
}

// ---------------------------------------------------------------------------
// GEMM 3 (SIMT fp32) + fused MSE: recons = Z_last (B x H) @ F_dec (H x D)
// ---------------------------------------------------------------------------
__global__ void __launch_bounds__(256) k_recons(const float* __restrict__ Fd,
                                                const float* __restrict__ Xp) {
    __shared__ float Asb[16][68];
    __shared__ float Bsb[16][68];
    __shared__ float red[256];

    const float* A = g_Zlast;
    const int tid = threadIdx.x;
    const int tx = tid & 15, ty = tid >> 4;
    const int m0 = blockIdx.y * 64, n0 = blockIdx.x * 64;
    const int arow = tid >> 2, akq = tid & 3;
    const int brow = tid >> 4, bq  = tid & 15;

    float acc[4][4] = {};

    for (int k0 = 0; k0 < HH; k0 += 16) {
        float4 av = *(const float4*)(A + (size_t)(m0 + arow) * HH + k0 + akq * 4);
        Asb[akq * 4 + 0][arow] = av.x;
        Asb[akq * 4 + 1][arow] = av.y;
        Asb[akq * 4 + 2][arow] = av.z;
        Asb[akq * 4 + 3][arow] = av.w;
        float4 bv = *(const float4*)(Fd + (size_t)(k0 + brow) * DD + n0 + bq * 4);
        *(float4*)&Bsb[brow][bq * 4] = bv;
        __syncthreads();
#pragma unroll
        for (int kk = 0; kk < 16; kk++) {
            const float4 a4 = *(const float4*)&Asb[kk][ty * 4];
            const float4 b4 = *(const float4*)&Bsb[kk][tx * 4];
            const float ar[4] = {a4.x, a4.y, a4.z, a4.w};
            const float br[4] = {b4.x, b4.y, b4.z, b4.w};
#pragma unroll
            for (int i = 0; i < 4; i++)
#pragma unroll
                for (int j = 0; j < 4; j++)
                    acc[i][j] += ar[i] * br[j];
        }
        __syncthreads();
    }
    float sse = 0.f;
#pragma unroll
    for (int i = 0; i < 4; i++)
#pragma unroll
        for (int j = 0; j < 4; j++) {
            const int b = m0 + ty * 4 + i;
            const int d = n0 + tx * 4 + j;
            const float x = Xp[((size_t)b * DD + d) * TT + TAUV];
            const float df = acc[i][j] - x;
            sse += df * df;
        }
    red[tid] = sse; __syncthreads();
    for (int s = 128; s; s >>= 1) { if (tid < s) red[tid] += red[tid + s]; __syncthreads(); }
    if (tid == 0) atomicAdd(&g_acc[2], (double)red[0]);
}

// ---------------------------------------------------------------------------
// Per-row exact top-100 via 8-bit radix select on |Zt|, then masked losses.
// ---------------------------------------------------------------------------
__global__ void __launch_bounds__(256) k_topk() {
    __shared__ float    zrow[HH];
    __shared__ unsigned hist[256];
    __shared__ unsigned s_prefix;
    __shared__ int      s_k;
    __shared__ float    red[256];

    const int b = blockIdx.x, tid = threadIdx.x;
    const float* zt = g_Zt + (size_t)b * HH;
    const float* zl = g_Zlast + (size_t)b * HH;

    for (int i = tid; i < HH; i += 256) zrow[i] = zt[i];
    __syncthreads();

    unsigned prefix = 0u;
    int kneed = KTOP;
    for (int shift = 24; shift >= 0; shift -= 8) {
        hist[tid] = 0u;
        __syncthreads();
        const unsigned hm = (shift == 24) ? 0u : (0xFFFFFFFFu << (shift + 8));
        for (int i = tid; i < HH; i += 256) {
            const unsigned bits = __float_as_uint(fabsf(zrow[i]));
            if ((bits & hm) == prefix) atomicAdd(&hist[(bits >> shift) & 255u], 1u);
        }
        __syncthreads();
        if (tid == 0) {
            int acc = 0;
            for (int bb = 255; bb >= 0; bb--) {
                acc += (int)hist[bb];
                if (acc >= kneed) {
                    s_prefix = prefix | ((unsigned)bb << shift);
                    s_k = kneed - (acc - (int)hist[bb]);
                    break;
                }
            }
        }
        __syncthreads();
        prefix = s_prefix;
        kneed = s_k;
        __syncthreads();
    }
    const unsigned T = prefix;
    if (tid == 0) {
        int r = kneed;
        for (int i = 0; i < HH; i++) {
            if (__float_as_uint(fabsf(zrow[i])) == T) {
                if (r > 0) r--; else zrow[i] = 0.f;
            }
        }
    }
    __syncthreads();

    float sse = 0.f, sab = 0.f, saz = 0.f;
    for (int i = tid; i < HH; i += 256) {
        const float z  = zrow[i];
        const float zm = (__float_as_uint(fabsf(z)) >= T) ? z : 0.f;
        const float zv = zl[i];
        const float d  = zm - zv;
        sse += d * d;
        sab += fabsf(d);
        saz += fabsf(zm);
    }
    red[tid] = sse; __syncthreads();
    for (int s = 128; s; s >>= 1) { if (tid < s) red[tid] += red[tid + s]; __syncthreads(); }
    if (tid == 0) atomicAdd(&g_acc[3], (double)red[0]);
    __syncthreads();
    red[tid] = sab; __syncthreads();
    for (int s = 128; s; s >>= 1) { if (tid < s) red[tid] += red[tid + s]; __syncthreads(); }
    if (tid == 0) atomicAdd(&g_acc[4], (double)red[0]);
    __syncthreads();
    red[tid] = saz; __syncthreads();
    for (int s = 128; s; s >>= 1) { if (tid < s) red[tid] += red[tid + s]; __syncthreads(); }
    if (tid == 0) atomicAdd(&g_acc[5], (double)red[0]);
}

// ---------------------------------------------------------------------------
__global__ void k_final(float* __restrict__ out) {
    if (threadIdx.x == 0 && blockIdx.x == 0) {
        out[0] = (float)(g_acc[2] / ((double)BB * DD));
        out[1] = (float)(g_acc[3] / ((double)BB * HH));
        out[2] = (float)(g_acc[4] / ((double)BB * HH));
        out[3] = (float)(g_acc[0] / ((double)HH * HH));
        out[4] = (float)(g_acc[1] / ((double)HH * HH));
        out[5] = (float)(g_acc[5] / ((double)BB * HH));
    }
}

// ---------------------------------------------------------------------------
extern "C" void kernel_launch(void* const* d_in, const int* in_sizes, int n_in,
                              void* d_out, int out_size) {
    (void)in_sizes; (void)n_in; (void)out_size;
    const float* Xp  = (const float*)d_in[0];
    const float* Fe  = (const float*)d_in[1];
    const float* Fd  = (const float*)d_in[2];
    const float* Bsw = (const float*)d_in[3];
    const float* Mw  = (const float*)d_in[4];
    float* out = (float*)d_out;

    cudaFuncSetAttribute(k_zp_mma, cudaFuncAttributeMaxDynamicSharedMemorySize, SMEM_MMA);
    cudaFuncSetAttribute(k_zt_f16, cudaFuncAttributeMaxDynamicSharedMemorySize, SMEM_MMA);

    k_init<<<1, 32>>>();
    k_conv_x<<<(BB * DD + 255) / 256, 256>>>(Xp);
    k_conv_fe<<<dim3(DD / 32, HH / 32), dim3(32, 8)>>>(Fe);
    k_convB<<<2048, 256>>>(Bsw, Mw);

    k_zp_mma<<<dim3(HH / 128, BB / 128, TT), 256, SMEM_MMA>>>();
    k_zlast<<<dim3(HH / 64, BB / 64), 256>>>(Fe);
    k_zt_f16<<<dim3(HH / 128, BB / 128), 256, SMEM_MMA>>>();

    k_recons<<<dim3(DD / 64, BB / 64), 256>>>(Fd, Xp);
    k_topk<<<BB, 256>>>();
    k_final<<<1, 32>>>(out);
}

// round 10
// speedup vs baseline: 5.2543x; 1.1117x over previous
#include <cuda_runtime.h>
#include <cuda_fp16.h>
#include <cstdint>
#include <math.h>

// Problem constants
#define BB   512
#define DD   1024
#define HH   4096
#define TT   21
#define TAUV 20
#define KTOP 100
#define KTOT (TT * HH)        // 86016 = fused contraction length for k_zt
#define BK   32
#define SST  40               // smem k-stride in halves (80 B, ldmatrix-friendly)
#define TEN_BYTES (128 * SST * 2)     // 10240 B per tensor per stage
#define STG  (2 * TEN_BYTES)          // A|B per stage = 20480
#define NST  4
#define SMEM_MMA (NST * STG)          // 81920

// ---------------------------------------------------------------------------
// Static device scratch (no allocations allowed)
// ---------------------------------------------------------------------------
__device__ __half g_X16[(size_t)TT * BB * DD];   // X fp16 [t][b][d]
__device__ float  g_X20[(size_t)BB * DD];        // X[:,:,20] fp32 compact
__device__ __half g_Fe16[(size_t)HH * DD];       // F_enc^T fp16 [h][d]
__device__ __half g_Fd16[(size_t)DD * HH];       // F_dec^T fp16 [d][h]
__device__ __half g_A16[(size_t)BB * KTOT];      // Zp fp16 [b][layer*H+h']
__device__ __half g_B16[(size_t)HH * KTOT];      // Bs/trilM fp16 [h][layer*H+d]
__device__ float g_Zlast[(size_t)BB * HH];       // fp32 Z_last (from k_zp t=20)
__device__ float g_Zt   [(size_t)BB * HH];
// 0=sum|Bs| 1=sum|trilM| 2=sseX 3=sseZ 4=sumAbsE 5=sum|Zt|
__device__ double g_acc[8];

// ---------------------------------------------------------------------------
// PTX helpers (base-target only: cp.async / ldmatrix / mma.sync)
// ---------------------------------------------------------------------------
__device__ __forceinline__ uint32_t smem_u32(const void* p) {
    uint32_t a;
    asm("{ .reg .u64 t; cvta.to.shared.u64 t, %1; cvt.u32.u64 %0, t; }"
        : "=r"(a) : "l"(p));
    return a;
}
__device__ __forceinline__ void cp_async16(uint32_t saddr, const void* gaddr) {
    asm volatile("cp.async.cg.shared.global [%0], [%1], 16;"
                 :: "r"(saddr), "l"(gaddr) : "memory");
}
__device__ __forceinline__ void cp_commit() {
    asm volatile("cp.async.commit_group;" ::: "memory");
}
__device__ __forceinline__ void cp_wait2() {
    asm volatile("cp.async.wait_group 2;" ::: "memory");
}
__device__ __forceinline__ void cp_wait1() {
    asm volatile("cp.async.wait_group 1;" ::: "memory");
}
__device__ __forceinline__ void cp_wait0() {
    asm volatile("cp.async.wait_group 0;" ::: "memory");
}
__device__ __forceinline__ void ldsm_x4(uint32_t* r, uint32_t addr) {
    asm volatile("ldmatrix.sync.aligned.m8n8.x4.shared.b16 {%0,%1,%2,%3}, [%4];"
                 : "=r"(r[0]), "=r"(r[1]), "=r"(r[2]), "=r"(r[3]) : "r"(addr));
}
__device__ __forceinline__ void mma_f16(float* c, const uint32_t* a, const uint32_t* b) {
    asm volatile(
        "mma.sync.aligned.m16n8k16.row.col.f32.f16.f16.f32 "
        "{%0,%1,%2,%3}, {%4,%5,%6,%7}, {%8,%9}, {%0,%1,%2,%3};"
        : "+f"(c[0]), "+f"(c[1]), "+f"(c[2]), "+f"(c[3])
        : "r"(a[0]), "r"(a[1]), "r"(a[2]), "r"(a[3]), "r"(b[0]), "r"(b[1]));
}

// ---------------------------------------------------------------------------
// fp16 1-term mainloop: acc += A*B over K = KT (per-row strides strA/strB).
// CTA 128x128, 8 warps (2m x 4n), warp tile 64x32, BK=32, 4-stage cp.async,
// single __syncthreads per chunk (issue moved after the barrier).
// ---------------------------------------------------------------------------
template <int KT>
__device__ __forceinline__ void mma_mainloop_f16(
    const __half* __restrict__ A, size_t strA,
    const __half* __restrict__ B, size_t strB,
    char* smem, float acc[4][4][4])
{
    const int tid  = threadIdx.x;
    const int lane = tid & 31, warp = tid >> 5;
    const int wm = warp & 1, wn = warp >> 1;
    const uint32_t sbase = smem_u32(smem);

    const int lrow = tid >> 1;
    const int lk   = (tid & 1) * 16;
    const size_t growA = (size_t)lrow * strA + lk;
    const size_t growB = (size_t)lrow * strB + lk;
    constexpr int NKT = KT / BK;

    auto issue = [&](int kt) {
        const int s = kt & (NST - 1);
        const size_t ka = growA + (size_t)kt * BK;
        const size_t kb = growB + (size_t)kt * BK;
        const uint32_t so = sbase + s * STG + (lrow * SST + lk) * 2;
        cp_async16(so,                  A + ka);
        cp_async16(so + 16,             A + ka + 8);
        cp_async16(so + TEN_BYTES,      B + kb);
        cp_async16(so + TEN_BYTES + 16, B + kb + 8);
        cp_commit();
    };

    issue(0); issue(1); issue(2);

    const int arow = lane & 15, akc = (lane >> 4) * 8;
    const int brow = lane & 15, bkc = (lane >> 4) * 8;

    for (int kt = 0; kt < NKT; kt++) {
        if (kt + 2 < NKT)      cp_wait2();
        else if (kt + 1 < NKT) cp_wait1();
        else                   cp_wait0();
        __syncthreads();
        if (kt + 3 < NKT) issue(kt + 3);   // overwrites stage (kt-1)&3: safe post-barrier

        const uint32_t tb = sbase + (kt & (NST - 1)) * STG;
#pragma unroll
        for (int kk = 0; kk < 2; kk++) {
            uint32_t a[4][4], bh[4][2];
#pragma unroll
            for (int mi = 0; mi < 4; mi++)
                ldsm_x4(a[mi], tb + ((wm * 64 + mi * 16 + arow) * SST + kk * 16 + akc) * 2);
#pragma unroll
            for (int p = 0; p < 2; p++) {
                uint32_t r[4];
                ldsm_x4(r, tb + TEN_BYTES +
                        ((wn * 32 + p * 16 + brow) * SST + kk * 16 + bkc) * 2);
                bh[2 * p][0] = r[0];     bh[2 * p][1] = r[2];
                bh[2 * p + 1][0] = r[1]; bh[2 * p + 1][1] = r[3];
            }
#pragma unroll
            for (int mi = 0; mi < 4; mi++)
#pragma unroll
                for (int ni = 0; ni < 4; ni++)
                    mma_f16(acc[mi][ni], a[mi], bh[ni]);
        }
    }
    __syncthreads();
}

// ---------------------------------------------------------------------------
__global__ void k_init() {
    if (threadIdx.x < 8) g_acc[threadIdx.x] = 0.0;
}

// Xp (B,D,T) t-fastest -> fp16 [t][b][d] + fp32 X20 [b][d]
__global__ void k_conv_x(const float* __restrict__ Xp) {
    int idx = blockIdx.x * blockDim.x + threadIdx.x;
    if (idx >= BB * DD) return;
    const float* s = Xp + (size_t)idx * TT;
#pragma unroll
    for (int t = 0; t < TT; t++) {
        const float v = s[t];
        g_X16[(size_t)t * BB * DD + idx] = __float2half_rn(v);
        if (t == TAUV) g_X20[idx] = v;
    }
}

// F_enc (D,H) -> transposed fp16 [h][d]
__global__ void k_conv_fe(const float* __restrict__ Fe) {
    __shared__ float tile[32][33];
    const int d0 = blockIdx.x * 32, h0 = blockIdx.y * 32;
    for (int r = threadIdx.y; r < 32; r += 8)
        tile[r][threadIdx.x] = Fe[(size_t)(d0 + r) * HH + h0 + threadIdx.x];
    __syncthreads();
    for (int r = threadIdx.y; r < 32; r += 8)
        g_Fe16[(size_t)(h0 + r) * DD + d0 + threadIdx.x] =
            __float2half_rn(tile[threadIdx.x][r]);
}

// F_dec (H,D) -> transposed fp16 [d][h]
__global__ void k_conv_fd(const float* __restrict__ Fd) {
    __shared__ float tile[32][33];
    const int h0 = blockIdx.x * 32, d0 = blockIdx.y * 32;
    for (int r = threadIdx.y; r < 32; r += 8)
        tile[r][threadIdx.x] = Fd[(size_t)(h0 + r) * DD + d0 + threadIdx.x];
    __syncthreads();
    for (int r = threadIdx.y; r < 32; r += 8)
        g_Fd16[(size_t)(d0 + r) * HH + h0 + threadIdx.x] =
            __float2half_rn(tile[threadIdx.x][r]);
}

// Bs (20,H,H) + tril(M,1) -> fp16 [h][layer*H+d], fused |Bs| / |M| sums
__global__ void __launch_bounds__(256) k_convB(const float* __restrict__ Bsw,
                                               const float* __restrict__ Mw) {
    __shared__ float red[256];
    const size_t total = (size_t)TT * HH * (HH / 4);   // float4 units
    float sBs = 0.f, sM = 0.f;
    for (size_t u = blockIdx.x * 256 + threadIdx.x; u < total;
         u += (size_t)gridDim.x * 256) {
        const int d4 = (int)(u & 1023);
        const int h  = (int)((u >> 10) & 4095);
        const int l  = (int)(u >> 22);
        float4 v;
        if (l < TAUV) {
            v = __ldcs((const float4*)(Bsw + (((size_t)l * HH + h) * HH + d4 * 4)));
            sBs += fabsf(v.x) + fabsf(v.y) + fabsf(v.z) + fabsf(v.w);
        } else {
            v = *(const float4*)(Mw + ((size_t)h * HH + d4 * 4));
            float* e = (float*)&v;
#pragma unroll
            for (int j = 0; j < 4; j++)
                if (d4 * 4 + j > h + 1) e[j] = 0.f;
            sM += fabsf(v.x) + fabsf(v.y) + fabsf(v.z) + fabsf(v.w);
        }
        union { __half2 b; uint32_t u; } p0, p1;
        p0.b = __floats2half2_rn(v.x, v.y);
        p1.b = __floats2half2_rn(v.z, v.w);
        *(uint2*)(g_B16 + (size_t)h * KTOT + (size_t)l * HH + d4 * 4) =
            make_uint2(p0.u, p1.u);
    }
    const int tid = threadIdx.x;
    red[tid] = sBs; __syncthreads();
    for (int s = 128; s; s >>= 1) { if (tid < s) red[tid] += red[tid + s]; __syncthreads(); }
    if (tid == 0) atomicAdd(&g_acc[0], (double)red[0]);
    __syncthreads();
    red[tid] = sM; __syncthreads();
    for (int s = 128; s; s >>= 1) { if (tid < s) red[tid] += red[tid + s]; __syncthreads(); }
    if (tid == 0) atomicAdd(&g_acc[1], (double)red[0]);
}

// ---------------------------------------------------------------------------
// GEMM 1 (fp16): Zp[t] = X[t] (B x D) @ F_enc^T (H x D)^T.
// Epilogue: fp16 Zp into the k_zt A layout (flip baked in) + fp32 Zlast @ t=20.
// ---------------------------------------------------------------------------
__global__ void __launch_bounds__(256, 1) k_zp_mma() {
    extern __shared__ char smem[];
    const int tid = threadIdx.x;
    const int lane = tid & 31, warp = tid >> 5;
    const int wm = warp & 1, wn = warp >> 1;
    const int t = blockIdx.z;
    const int m0 = blockIdx.y * 128, n0 = blockIdx.x * 128;

    float acc[4][4][4] = {};
    mma_mainloop_f16<DD>(g_X16 + ((size_t)t * BB + m0) * DD, DD,
                         g_Fe16 + (size_t)n0 * DD, DD,
                         smem, acc);

    const int layer = (t < TAUV) ? (TAUV - 1 - t) : TAUV;
    const int mb = m0 + wm * 64 + (lane >> 2);
    const int nb = n0 + wn * 32 + (lane & 3) * 2;
#pragma unroll
    for (int mi = 0; mi < 4; mi++)
#pragma unroll
        for (int ni = 0; ni < 4; ni++)
#pragma unroll
            for (int half = 0; half < 2; half++) {
                const int m = mb + mi * 16 + half * 8;
                const int n = nb + ni * 8;
                const float f0 = acc[mi][ni][half * 2];
                const float f1 = acc[mi][ni][half * 2 + 1];
                const size_t o = (size_t)m * KTOT + (size_t)layer * HH + n;
                *(__half2*)(g_A16 + o) = __floats2half2_rn(f0, f1);
                if (t == TAUV)
                    *(float2*)(g_Zlast + (size_t)m * HH + n) = make_float2(f0, f1);
            }
}

// ---------------------------------------------------------------------------
// GEMM 2 (fp16, fused): Zt (B x H) over K = 21*4096.
// ---------------------------------------------------------------------------
__global__ void __launch_bounds__(256, 1) k_zt_f16() {
    extern __shared__ char smem[];
    const int tid = threadIdx.x;
    const int lane = tid & 31, warp = tid >> 5;
    const int wm = warp & 1, wn = warp >> 1;
    const int m0 = blockIdx.y * 128, n0 = blockIdx.x * 128;

    float acc[4][4][4] = {};
    mma_mainloop_f16<KTOT>(g_A16 + (size_t)m0 * KTOT, KTOT,
                           g_B16 + (size_t)n0 * KTOT, KTOT,
                           smem, acc);

    const int mb = m0 + wm * 64 + (lane >> 2);
    const int nb = n0 + wn * 32 + (lane & 3) * 2;
#pragma unroll
    for (int mi = 0; mi < 4; mi++)
#pragma unroll
        for (int ni = 0; ni < 4; ni++)
#pragma unroll
            for (int half = 0; half < 2; half++) {
                const int m = mb + mi * 16 + half * 8;
                const int n = nb + ni * 8;
                *(float2*)(g_Zt + (size_t)m * HH + n) =
                    make_float2(acc[mi][ni][half * 2], acc[mi][ni][half * 2 + 1]);
            }
}

// ---------------------------------------------------------------------------
// GEMM 3 (fp16, fused SSE): recons = Zp[20] (B x H) @ F_dec^T (D x H)^T,
// compared against X20 in fp32; only the SSE leaves the kernel.
// A = layer-20 slice of g_A16 (row stride KTOT).
// ---------------------------------------------------------------------------
__global__ void __launch_bounds__(256, 1) k_recons_f16() {
    extern __shared__ char smem[];
    const int tid = threadIdx.x;
    const int lane = tid & 31, warp = tid >> 5;
    const int wm = warp & 1, wn = warp >> 1;
    const int m0 = blockIdx.y * 128, n0 = blockIdx.x * 128;
    __shared__ float red[256];

    float acc[4][4][4] = {};
    mma_mainloop_f16<HH>(g_A16 + (size_t)m0 * KTOT + (size_t)TAUV * HH, KTOT,
                         g_Fd16 + (size_t)n0 * HH, HH,
                         smem, acc);

    const int mb = m0 + wm * 64 + (lane >> 2);
    const int nb = n0 + wn * 32 + (lane & 3) * 2;
    float sse = 0.f;
#pragma unroll
    for (int mi = 0; mi < 4; mi++)
#pragma unroll
        for (int ni = 0; ni < 4; ni++)
#pragma unroll
            for (int half = 0; half < 2; half++) {
                const int m = mb + mi * 16 + half * 8;
                const int n = nb + ni * 8;
                const float2 x = *(const float2*)(g_X20 + (size_t)m * DD + n);
                const float d0 = acc[mi][ni][half * 2] - x.x;
                const float d1 = acc[mi][ni][half * 2 + 1] - x.y;
                sse += d0 * d0 + d1 * d1;
            }
    red[tid] = sse; __syncthreads();
    for (int s = 128; s; s >>= 1) { if (tid < s) red[tid] += red[tid + s]; __syncthreads(); }
    if (tid == 0) atomicAdd(&g_acc[2], (double)red[0]);
}

// ---------------------------------------------------------------------------
// Per-row exact top-100 via 8-bit radix select on |Zt|, then masked losses.
// ---------------------------------------------------------------------------
__global__ void __launch_bounds__(256) k_topk() {
    __shared__ float    zrow[HH];
    __shared__ unsigned hist[256];
    __shared__ unsigned s_prefix;
    __shared__ int      s_k;
    __shared__ float    red[256];

    const int b = blockIdx.x, tid = threadIdx.x;
    const float* zt = g_Zt + (size_t)b * HH;
    const float* zl = g_Zlast + (size_t)b * HH;

    for (int i = tid; i < HH; i += 256) zrow[i] = zt[i];
    __syncthreads();

    unsigned prefix = 0u;
    int kneed = KTOP;
    for (int shift = 24; shift >= 0; shift -= 8) {
        hist[tid] = 0u;
        __syncthreads();
        const unsigned hm = (shift == 24) ? 0u : (0xFFFFFFFFu << (shift + 8));
        for (int i = tid; i < HH; i += 256) {
            const unsigned bits = __float_as_uint(fabsf(zrow[i]));
            if ((bits & hm) == prefix) atomicAdd(&hist[(bits >> shift) & 255u], 1u);
        }
        __syncthreads();
        if (tid == 0) {
            int acc = 0;
            for (int bb = 255; bb >= 0; bb--) {
                acc += (int)hist[bb];
                if (acc >= kneed) {
                    s_prefix = prefix | ((unsigned)bb << shift);
                    s_k = kneed - (acc - (int)hist[bb]);
                    break;
                }
            }
        }
        __syncthreads();
        prefix = s_prefix;
        kneed = s_k;
        __syncthreads();
    }
    const unsigned T = prefix;
    if (tid == 0) {
        int r = kneed;
        for (int i = 0; i < HH; i++) {
            if (__float_as_uint(fabsf(zrow[i])) == T) {
                if (r > 0) r--; else zrow[i] = 0.f;
            }
        }
    }
    __syncthreads();

    float sse = 0.f, sab = 0.f, saz = 0.f;
    for (int i = tid; i < HH; i += 256) {
        const float z  = zrow[i];
        const float zm = (__float_as_uint(fabsf(z)) >= T) ? z : 0.f;
        const float zv = zl[i];
        const float d  = zm - zv;
        sse += d * d;
        sab += fabsf(d);
        saz += fabsf(zm);
    }
    red[tid] = sse; __syncthreads();
    for (int s = 128; s; s >>= 1) { if (tid < s) red[tid] += red[tid + s]; __syncthreads(); }
    if (tid == 0) atomicAdd(&g_acc[3], (double)red[0]);
    __syncthreads();
    red[tid] = sab; __syncthreads();
    for (int s = 128; s; s >>= 1) { if (tid < s) red[tid] += red[tid + s]; __syncthreads(); }
    if (tid == 0) atomicAdd(&g_acc[4], (double)red[0]);
    __syncthreads();
    red[tid] = saz; __syncthreads();
    for (int s = 128; s; s >>= 1) { if (tid < s) red[tid] += red[tid + s]; __syncthreads(); }
    if (tid == 0) atomicAdd(&g_acc[5], (double)red[0]);
}

// ---------------------------------------------------------------------------
__global__ void k_final(float* __restrict__ out) {
    if (threadIdx.x == 0 && blockIdx.x == 0) {
        out[0] = (float)(g_acc[2] / ((double)BB * DD));
        out[1] = (float)(g_acc[3] / ((double)BB * HH));
        out[2] = (float)(g_acc[4] / ((double)BB * HH));
        out[3] = (float)(g_acc[0] / ((double)HH * HH));
        out[4] = (float)(g_acc[1] / ((double)HH * HH));
        out[5] = (float)(g_acc[5] / ((double)BB * HH));
    }
}

// ---------------------------------------------------------------------------
extern "C" void kernel_launch(void* const* d_in, const int* in_sizes, int n_in,
                              void* d_out, int out_size) {
    (void)in_sizes; (void)n_in; (void)out_size;
    const float* Xp  = (const float*)d_in[0];
    const float* Fe  = (const float*)d_in[1];
    const float* Fd  = (const float*)d_in[2];
    const float* Bsw = (const float*)d_in[3];
    const float* Mw  = (const float*)d_in[4];
    float* out = (float*)d_out;

    cudaFuncSetAttribute(k_zp_mma,     cudaFuncAttributeMaxDynamicSharedMemorySize, SMEM_MMA);
    cudaFuncSetAttribute(k_zt_f16,     cudaFuncAttributeMaxDynamicSharedMemorySize, SMEM_MMA);
    cudaFuncSetAttribute(k_recons_f16, cudaFuncAttributeMaxDynamicSharedMemorySize, SMEM_MMA);

    k_init<<<1, 32>>>();
    k_conv_x<<<(BB * DD + 255) / 256, 256>>>(Xp);
    k_conv_fe<<<dim3(DD / 32, HH / 32), dim3(32, 8)>>>(Fe);
    k_conv_fd<<<dim3(HH / 32, DD / 32), dim3(32, 8)>>>(Fd);
    k_convB<<<2048, 256>>>(Bsw, Mw);

    k_zp_mma<<<dim3(HH / 128, BB / 128, TT), 256, SMEM_MMA>>>();
    k_zt_f16<<<dim3(HH / 128, BB / 128), 256, SMEM_MMA>>>();
    k_recons_f16<<<dim3(DD / 128, BB / 128), 256, SMEM_MMA>>>();

    k_topk<<<BB, 256>>>();
    k_final<<<1, 32>>>(out);
}